// round 1
// baseline (speedup 1.0000x reference)
#include <cuda_runtime.h>
#include <math.h>

#define BATCH 8
#define CIN   256
#define NPIX  16384
#define HEADS 4
#define DH    32
#define HID   128

// ---------------- scratch (device globals; no allocation allowed) ------------
__device__ float g_kv[(long)BATCH * 256 * NPIX];        // k rows 0..127, v rows 128..255
__device__ float g_ctx[BATCH * HEADS * DH * DH];        // exp-weighted context accumulators
__device__ float g_z[BATCH * HEADS * DH];               // softmax denominators
__device__ float g_weff[BATCH * 256 * HID];             // w_out folded with context
__device__ float g_wtot[BATCH * 256 * 256];             // full effective per-batch weight

// ---------------- zero the atomically-accumulated buffers --------------------
__global__ void k_zero() {
    int i = blockIdx.x * blockDim.x + threadIdx.x;
    if (i < BATCH * HEADS * DH * DH) g_ctx[i] = 0.f;
    if (i < BATCH * HEADS * DH)      g_z[i]   = 0.f;
}

// ---------------- generic batched SGEMM: C[b] = A[b] @ X[b] (+bias) ----------
// A: [M,K] row-major, X: [K,N] row-major, C: [M,N] row-major.
// BM=BN=128, BK=16, 256 threads, 8x8 per thread.
__global__ __launch_bounds__(256, 2)
void k_sgemm(const float* __restrict__ A, long sA,
             const float* __restrict__ X, long sX,
             float* __restrict__ C, long sC,
             const float* __restrict__ bias,
             int M, int K, int N)
{
    const int BM = 128, BN = 128, BK = 16;
    __shared__ float As[BK][BM];     // transposed A tile
    __shared__ float Xs[BK][BN];

    int b = blockIdx.z;
    const float* Ab = A + (long)b * sA;
    const float* Xb = X + (long)b * sX;
    float*       Cb = C + (long)b * sC;
    int m0 = blockIdx.y * BM, n0 = blockIdx.x * BN;
    int tid = threadIdx.x;
    int ty = tid >> 4, tx = tid & 15;

    float acc[8][8];
#pragma unroll
    for (int i = 0; i < 8; i++)
#pragma unroll
        for (int j = 0; j < 8; j++) acc[i][j] = 0.f;

    for (int k0 = 0; k0 < K; k0 += BK) {
        // A tile: 128 rows x 16 k, via float4, stored transposed
#pragma unroll
        for (int i = 0; i < 2; i++) {
            int f = i * 256 + tid;
            int m = f >> 2, k4 = (f & 3) << 2;
            float4 v = *(const float4*)&Ab[(long)(m0 + m) * K + k0 + k4];
            As[k4 + 0][m] = v.x; As[k4 + 1][m] = v.y;
            As[k4 + 2][m] = v.z; As[k4 + 3][m] = v.w;
        }
        // X tile: 16 k x 128 n, coalesced float4
#pragma unroll
        for (int i = 0; i < 2; i++) {
            int f = i * 256 + tid;
            int kk = f >> 5, n4 = (f & 31) << 2;
            *(float4*)&Xs[kk][n4] = *(const float4*)&Xb[(long)(k0 + kk) * N + n0 + n4];
        }
        __syncthreads();

#pragma unroll
        for (int kk = 0; kk < BK; kk++) {
            float4 a0 = *(const float4*)&As[kk][ty * 8];
            float4 a1 = *(const float4*)&As[kk][ty * 8 + 4];
            float4 x0 = *(const float4*)&Xs[kk][tx * 8];
            float4 x1 = *(const float4*)&Xs[kk][tx * 8 + 4];
            float ar[8] = {a0.x, a0.y, a0.z, a0.w, a1.x, a1.y, a1.z, a1.w};
            float xr[8] = {x0.x, x0.y, x0.z, x0.w, x1.x, x1.y, x1.z, x1.w};
#pragma unroll
            for (int i = 0; i < 8; i++)
#pragma unroll
                for (int j = 0; j < 8; j++)
                    acc[i][j] = fmaf(ar[i], xr[j], acc[i][j]);
        }
        __syncthreads();
    }

#pragma unroll
    for (int i = 0; i < 8; i++) {
        int m = m0 + ty * 8 + i;
        float bv = bias ? bias[m] : 0.f;
#pragma unroll
        for (int j = 0; j < 8; j += 4) {
            int n = n0 + tx * 8 + j;
            float4 v;
            v.x = acc[i][j + 0] + bv; v.y = acc[i][j + 1] + bv;
            v.z = acc[i][j + 2] + bv; v.w = acc[i][j + 3] + bv;
            *(float4*)&Cb[(long)m * N + n] = v;
        }
    }
}

// ---------------- context partials: ctx[d,e] += sum_n exp(k[d,n]) v[e,n] -----
// grid (NPIX/128, HEADS, BATCH), 256 threads. Tile Tn=128.
#define TN2 128
__global__ __launch_bounds__(256)
void k_context()
{
    __shared__ float ek[32][TN2 + 1];
    __shared__ float vs[32][TN2 + 1];
    int b = blockIdx.z, h = blockIdx.y;
    long n0 = (long)blockIdx.x * TN2;
    const float* kb = g_kv + ((long)b * 256 + h * 32) * NPIX + n0;
    const float* vb = g_kv + ((long)b * 256 + 128 + h * 32) * NPIX + n0;
    int tid = threadIdx.x;

    // fill: each thread does one row (tid/8), 16 cols; k~N(0,1) so bare exp is safe
    int row = tid >> 3;
    int c0 = (tid & 7) << 4;
    float zp = 0.f;
#pragma unroll
    for (int c = 0; c < 16; c += 4) {
        float4 kk = *(const float4*)&kb[(long)row * NPIX + c0 + c];
        float e0 = expf(kk.x), e1 = expf(kk.y), e2 = expf(kk.z), e3 = expf(kk.w);
        ek[row][c0 + c + 0] = e0; ek[row][c0 + c + 1] = e1;
        ek[row][c0 + c + 2] = e2; ek[row][c0 + c + 3] = e3;
        zp += (e0 + e1) + (e2 + e3);
        float4 vv = *(const float4*)&vb[(long)row * NPIX + c0 + c];
        vs[row][c0 + c + 0] = vv.x; vs[row][c0 + c + 1] = vv.y;
        vs[row][c0 + c + 2] = vv.z; vs[row][c0 + c + 3] = vv.w;
    }
    atomicAdd(&g_z[(b * HEADS + h) * DH + row], zp);
    __syncthreads();

    // 4 groups of 64 threads; each group handles 32 n-columns; 4x4 outer product
    int g  = tid >> 6;
    int tg = tid & 63;
    int td = (tg >> 3) << 2;   // d base (0..28)
    int te = (tg & 7)  << 2;   // e base (0..28)
    int nb = g << 5;
    float acc[4][4];
#pragma unroll
    for (int i = 0; i < 4; i++)
#pragma unroll
        for (int j = 0; j < 4; j++) acc[i][j] = 0.f;

#pragma unroll 4
    for (int n = 0; n < 32; n++) {
        float a0 = ek[td + 0][nb + n], a1 = ek[td + 1][nb + n];
        float a2 = ek[td + 2][nb + n], a3 = ek[td + 3][nb + n];
        float b0 = vs[te + 0][nb + n], b1 = vs[te + 1][nb + n];
        float b2 = vs[te + 2][nb + n], b3 = vs[te + 3][nb + n];
        acc[0][0] = fmaf(a0, b0, acc[0][0]); acc[0][1] = fmaf(a0, b1, acc[0][1]);
        acc[0][2] = fmaf(a0, b2, acc[0][2]); acc[0][3] = fmaf(a0, b3, acc[0][3]);
        acc[1][0] = fmaf(a1, b0, acc[1][0]); acc[1][1] = fmaf(a1, b1, acc[1][1]);
        acc[1][2] = fmaf(a1, b2, acc[1][2]); acc[1][3] = fmaf(a1, b3, acc[1][3]);
        acc[2][0] = fmaf(a2, b0, acc[2][0]); acc[2][1] = fmaf(a2, b1, acc[2][1]);
        acc[2][2] = fmaf(a2, b2, acc[2][2]); acc[2][3] = fmaf(a2, b3, acc[2][3]);
        acc[3][0] = fmaf(a3, b0, acc[3][0]); acc[3][1] = fmaf(a3, b1, acc[3][1]);
        acc[3][2] = fmaf(a3, b2, acc[3][2]); acc[3][3] = fmaf(a3, b3, acc[3][3]);
    }
    float* cp = g_ctx + (long)(b * HEADS + h) * DH * DH;
#pragma unroll
    for (int i = 0; i < 4; i++)
#pragma unroll
        for (int j = 0; j < 4; j++)
            atomicAdd(&cp[(td + i) * DH + te + j], acc[i][j]);
}

// ---------------- fold: W_eff[b][o][h*32+d] = sum_e w_out[o][h*32+e]*ctxn[h][d][e]
// grid (BATCH, 8 o-chunks), 256 threads
__global__ __launch_bounds__(256)
void k_weff(const float* __restrict__ w_out)
{
    __shared__ float ctxn[HEADS][DH][DH + 1];
    __shared__ float zinv[HEADS * DH];
    int b = blockIdx.x, oc = blockIdx.y;
    int tid = threadIdx.x;
    if (tid < 128) zinv[tid] = 1.0f / g_z[b * 128 + tid];
    __syncthreads();
    for (int i = tid; i < 4096; i += 256) {
        int h = i >> 10, d = (i >> 5) & 31, e = i & 31;
        ctxn[h][d][e] = g_ctx[b * 4096 + i] * zinv[h * 32 + d];
    }
    __syncthreads();
    for (int i = tid; i < 32 * 128; i += 256) {
        int ol = i >> 7;
        int hd = i & 127;
        int h = hd >> 5, d = hd & 31;
        int o = oc * 32 + ol;
        const float* wrow = w_out + o * HID + h * 32;
        float s = 0.f;
#pragma unroll
        for (int e = 0; e < 32; e++) s = fmaf(wrow[e], ctxn[h][d][e], s);
        g_weff[((long)b * 256 + o) * HID + hd] = s;
    }
}

// ---------------- launch --------------------------------------------------
extern "C" void kernel_launch(void* const* d_in, const int* in_sizes, int n_in,
                              void* d_out, int out_size)
{
    // match inputs by element count (all distinct): x, w_qkv, w_out, b_out
    const float *x = nullptr, *w_qkv = nullptr, *w_out = nullptr, *b_out = nullptr;
    for (int i = 0; i < n_in; i++) {
        const float* p = (const float*)d_in[i];
        if      (in_sizes[i] == BATCH * CIN * NPIX) x     = p;
        else if (in_sizes[i] == 3 * HID * CIN)      w_qkv = p;
        else if (in_sizes[i] == CIN * HID)          w_out = p;
        else if (in_sizes[i] == CIN)                b_out = p;
    }
    float* out = (float*)d_out;

    float *kv, *weff, *wtot;
    cudaGetSymbolAddress((void**)&kv,   g_kv);
    cudaGetSymbolAddress((void**)&weff, g_weff);
    cudaGetSymbolAddress((void**)&wtot, g_wtot);

    // 0) zero accumulators
    k_zero<<<132, 256>>>();

    // 1) kv = W_kv @ x   (k,v rows of w_qkv = rows 128..383)
    k_sgemm<<<dim3(NPIX / 128, 2, BATCH), 256>>>(
        w_qkv + 128 * CIN, 0,
        x, (long)CIN * NPIX,
        kv, (long)256 * NPIX,
        nullptr, 256, CIN, NPIX);

    // 2) context partials (exp-softmax numerator + denominator via atomics)
    k_context<<<dim3(NPIX / TN2, HEADS, BATCH), 256>>>();

    // 3a) fold w_out with normalized context -> W_eff [b,256,128]
    k_weff<<<dim3(BATCH, 8), 256>>>(w_out);

    // 3b) W_total[b] = W_eff[b] @ W_q   (W_q = w_qkv rows 0..127, [128,256])
    k_sgemm<<<dim3(2, 2, BATCH), 256>>>(
        weff, (long)256 * HID,
        w_qkv, 0,
        wtot, (long)256 * 256,
        nullptr, 256, HID, 256);

    // 4) y[b] = W_total[b] @ x[b] + b_out
    k_sgemm<<<dim3(NPIX / 128, 2, BATCH), 256>>>(
        wtot, (long)256 * 256,
        x, (long)CIN * NPIX,
        out, (long)256 * NPIX,
        b_out, 256, CIN, NPIX);
}

// round 2
// speedup vs baseline: 1.8321x; 1.8321x over previous
#include <cuda_runtime.h>
#include <math.h>
#include <stdint.h>

#define BATCH 8
#define CIN   256
#define NPIX  16384
#define HEADS 4
#define DH    32
#define HID   128

// ---------------- scratch (device globals; no allocation allowed) ------------
__device__ float g_kv[(long)BATCH * 256 * NPIX];        // k rows 0..127, v rows 128..255
__device__ float g_ctx[BATCH * HEADS * DH * DH];        // exp-weighted context accumulators
__device__ float g_z[BATCH * HEADS * DH];               // softmax denominators
__device__ float g_weff[BATCH * 256 * HID];             // w_out folded with context
__device__ float g_wtot[BATCH * 256 * 256];             // full effective per-batch weight

__device__ __forceinline__ uint32_t cvt_tf32(float x) {
    uint32_t u;
    asm("cvt.rna.tf32.f32 %0, %1;" : "=r"(u) : "f"(x));
    return u;
}

// ---------------- zero the atomically-accumulated buffers --------------------
__global__ void k_zero() {
    int i = blockIdx.x * blockDim.x + threadIdx.x;
    if (i < BATCH * HEADS * DH * DH) g_ctx[i] = 0.f;
    if (i < BATCH * HEADS * DH)      g_z[i]   = 0.f;
}

// ---------------- tf32 tensor-core batched SGEMM: C[b] = A[b]@X[b] (+bias) ---
// A: [M,K] row-major, X: [K,N] row-major, C: [M,N] row-major.
// BM=BN=128, BK=32, 256 threads (8 warps, 2x4), warp tile 64x32, fp32 accum.
__global__ __launch_bounds__(256, 2)
void k_sgemm_tc(const float* __restrict__ A, long sA,
                const float* __restrict__ X, long sX,
                float* __restrict__ C, long sC,
                const float* __restrict__ bias,
                int M, int K, int N)
{
    const int BM = 128, BN = 128, BK = 32;
    __shared__ uint32_t As[BK][BM + 4];   // A transposed: As[k][m], stride 132
    __shared__ uint32_t Bs[BK][BN + 4];   // Bs[k][n], stride 132

    int b = blockIdx.z;
    const float* Ab = A + (long)b * sA;
    const float* Xb = X + (long)b * sX;
    float*       Cb = C + (long)b * sC;
    int m0 = blockIdx.y * BM, n0 = blockIdx.x * BN;
    int tid  = threadIdx.x;
    int wid  = tid >> 5, lane = tid & 31;
    int g4   = lane >> 2, q = lane & 3;
    int wm   = (wid >> 2) * 64;     // warp m offset (0 or 64)
    int wn   = (wid & 3) * 32;      // warp n offset (0,32,64,96)

    float acc[4][4][4];
#pragma unroll
    for (int i = 0; i < 4; i++)
#pragma unroll
        for (int j = 0; j < 4; j++)
#pragma unroll
            for (int r = 0; r < 4; r++) acc[i][j][r] = 0.f;

    for (int k0 = 0; k0 < K; k0 += BK) {
        // ---- A tile: 128 rows x 32 k, 4 float4/thread, store transposed+tf32
#pragma unroll
        for (int i = 0; i < 4; i++) {
            int f  = i * 256 + tid;          // 0..1023 float4 slots
            int m  = f >> 3, k4 = (f & 7) << 2;
            float4 v = *(const float4*)&Ab[(long)(m0 + m) * K + k0 + k4];
            As[k4 + 0][m] = cvt_tf32(v.x); As[k4 + 1][m] = cvt_tf32(v.y);
            As[k4 + 2][m] = cvt_tf32(v.z); As[k4 + 3][m] = cvt_tf32(v.w);
        }
        // ---- B tile: 32 k x 128 n, coalesced float4, tf32
#pragma unroll
        for (int i = 0; i < 4; i++) {
            int f  = i * 256 + tid;
            int kk = f >> 5, n4 = (f & 31) << 2;
            float4 v = *(const float4*)&Xb[(long)(k0 + kk) * N + n0 + n4];
            uint4 u;
            u.x = cvt_tf32(v.x); u.y = cvt_tf32(v.y);
            u.z = cvt_tf32(v.z); u.w = cvt_tf32(v.w);
            *(uint4*)&Bs[kk][n4] = u;
        }
        __syncthreads();

#pragma unroll
        for (int ks = 0; ks < BK; ks += 8) {
            uint32_t af[4][4];
#pragma unroll
            for (int mf = 0; mf < 4; mf++) {
                int mb = wm + mf * 16;
                af[mf][0] = As[ks + q    ][mb + g4    ];
                af[mf][1] = As[ks + q    ][mb + g4 + 8];
                af[mf][2] = As[ks + q + 4][mb + g4    ];
                af[mf][3] = As[ks + q + 4][mb + g4 + 8];
            }
#pragma unroll
            for (int nf = 0; nf < 4; nf++) {
                int nb = wn + nf * 8;
                uint32_t b0 = Bs[ks + q    ][nb + g4];
                uint32_t b1 = Bs[ks + q + 4][nb + g4];
#pragma unroll
                for (int mf = 0; mf < 4; mf++) {
                    asm volatile(
                        "mma.sync.aligned.m16n8k8.row.col.f32.tf32.tf32.f32 "
                        "{%0,%1,%2,%3},{%4,%5,%6,%7},{%8,%9},{%0,%1,%2,%3};"
                        : "+f"(acc[mf][nf][0]), "+f"(acc[mf][nf][1]),
                          "+f"(acc[mf][nf][2]), "+f"(acc[mf][nf][3])
                        : "r"(af[mf][0]), "r"(af[mf][1]),
                          "r"(af[mf][2]), "r"(af[mf][3]),
                          "r"(b0), "r"(b1));
                }
            }
        }
        __syncthreads();
    }

    // ---- epilogue: c0,c1 at (row,2q),(row,2q+1); c2,c3 at row+8
#pragma unroll
    for (int mf = 0; mf < 4; mf++) {
        int mrow = m0 + wm + mf * 16 + g4;
        float bv0 = bias ? bias[mrow]     : 0.f;
        float bv1 = bias ? bias[mrow + 8] : 0.f;
#pragma unroll
        for (int nf = 0; nf < 4; nf++) {
            int nc = n0 + wn + nf * 8 + 2 * q;
            float2 v0 = { acc[mf][nf][0] + bv0, acc[mf][nf][1] + bv0 };
            float2 v1 = { acc[mf][nf][2] + bv1, acc[mf][nf][3] + bv1 };
            *(float2*)&Cb[(long)mrow * N + nc]       = v0;
            *(float2*)&Cb[(long)(mrow + 8) * N + nc] = v1;
        }
    }
}

// ---------------- context partials: ctx[d,e] += sum_n exp(k[d,n]) v[e,n] -----
#define TN2 128
__global__ __launch_bounds__(256)
void k_context()
{
    __shared__ float ek[32][TN2 + 1];
    __shared__ float vs[32][TN2 + 1];
    int b = blockIdx.z, h = blockIdx.y;
    long n0 = (long)blockIdx.x * TN2;
    const float* kb = g_kv + ((long)b * 256 + h * 32) * NPIX + n0;
    const float* vb = g_kv + ((long)b * 256 + 128 + h * 32) * NPIX + n0;
    int tid = threadIdx.x;

    int row = tid >> 3;
    int c0 = (tid & 7) << 4;
    float zp = 0.f;
#pragma unroll
    for (int c = 0; c < 16; c += 4) {
        float4 kk = *(const float4*)&kb[(long)row * NPIX + c0 + c];
        float e0 = expf(kk.x), e1 = expf(kk.y), e2 = expf(kk.z), e3 = expf(kk.w);
        ek[row][c0 + c + 0] = e0; ek[row][c0 + c + 1] = e1;
        ek[row][c0 + c + 2] = e2; ek[row][c0 + c + 3] = e3;
        zp += (e0 + e1) + (e2 + e3);
        float4 vv = *(const float4*)&vb[(long)row * NPIX + c0 + c];
        vs[row][c0 + c + 0] = vv.x; vs[row][c0 + c + 1] = vv.y;
        vs[row][c0 + c + 2] = vv.z; vs[row][c0 + c + 3] = vv.w;
    }
    atomicAdd(&g_z[(b * HEADS + h) * DH + row], zp);
    __syncthreads();

    int g  = tid >> 6;
    int tg = tid & 63;
    int td = (tg >> 3) << 2;
    int te = (tg & 7)  << 2;
    int nb = g << 5;
    float acc[4][4];
#pragma unroll
    for (int i = 0; i < 4; i++)
#pragma unroll
        for (int j = 0; j < 4; j++) acc[i][j] = 0.f;

#pragma unroll 4
    for (int n = 0; n < 32; n++) {
        float a0 = ek[td + 0][nb + n], a1 = ek[td + 1][nb + n];
        float a2 = ek[td + 2][nb + n], a3 = ek[td + 3][nb + n];
        float b0 = vs[te + 0][nb + n], b1 = vs[te + 1][nb + n];
        float b2 = vs[te + 2][nb + n], b3 = vs[te + 3][nb + n];
        acc[0][0] = fmaf(a0, b0, acc[0][0]); acc[0][1] = fmaf(a0, b1, acc[0][1]);
        acc[0][2] = fmaf(a0, b2, acc[0][2]); acc[0][3] = fmaf(a0, b3, acc[0][3]);
        acc[1][0] = fmaf(a1, b0, acc[1][0]); acc[1][1] = fmaf(a1, b1, acc[1][1]);
        acc[1][2] = fmaf(a1, b2, acc[1][2]); acc[1][3] = fmaf(a1, b3, acc[1][3]);
        acc[2][0] = fmaf(a2, b0, acc[2][0]); acc[2][1] = fmaf(a2, b1, acc[2][1]);
        acc[2][2] = fmaf(a2, b2, acc[2][2]); acc[2][3] = fmaf(a2, b3, acc[2][3]);
        acc[3][0] = fmaf(a3, b0, acc[3][0]); acc[3][1] = fmaf(a3, b1, acc[3][1]);
        acc[3][2] = fmaf(a3, b2, acc[3][2]); acc[3][3] = fmaf(a3, b3, acc[3][3]);
    }
    float* cp = g_ctx + (long)(b * HEADS + h) * DH * DH;
#pragma unroll
    for (int i = 0; i < 4; i++)
#pragma unroll
        for (int j = 0; j < 4; j++)
            atomicAdd(&cp[(td + i) * DH + te + j], acc[i][j]);
}

// ---------------- fold: W_eff[b][o][h*32+d] = sum_e w_out[o][h*32+e]*ctxn[h][d][e]
__global__ __launch_bounds__(256)
void k_weff(const float* __restrict__ w_out)
{
    __shared__ float ctxn[HEADS][DH][DH + 1];
    __shared__ float zinv[HEADS * DH];
    int b = blockIdx.x, oc = blockIdx.y;
    int tid = threadIdx.x;
    if (tid < 128) zinv[tid] = 1.0f / g_z[b * 128 + tid];
    __syncthreads();
    for (int i = tid; i < 4096; i += 256) {
        int h = i >> 10, d = (i >> 5) & 31, e = i & 31;
        ctxn[h][d][e] = g_ctx[b * 4096 + i] * zinv[h * 32 + d];
    }
    __syncthreads();
    for (int i = tid; i < 32 * 128; i += 256) {
        int ol = i >> 7;
        int hd = i & 127;
        int h = hd >> 5, d = hd & 31;
        int o = oc * 32 + ol;
        const float* wrow = w_out + o * HID + h * 32;
        float s = 0.f;
#pragma unroll
        for (int e = 0; e < 32; e++) s = fmaf(wrow[e], ctxn[h][d][e], s);
        g_weff[((long)b * 256 + o) * HID + hd] = s;
    }
}

// ---------------- launch --------------------------------------------------
extern "C" void kernel_launch(void* const* d_in, const int* in_sizes, int n_in,
                              void* d_out, int out_size)
{
    const float *x = nullptr, *w_qkv = nullptr, *w_out = nullptr, *b_out = nullptr;
    for (int i = 0; i < n_in; i++) {
        const float* p = (const float*)d_in[i];
        if      (in_sizes[i] == BATCH * CIN * NPIX) x     = p;
        else if (in_sizes[i] == 3 * HID * CIN)      w_qkv = p;
        else if (in_sizes[i] == CIN * HID)          w_out = p;
        else if (in_sizes[i] == CIN)                b_out = p;
    }
    float* out = (float*)d_out;

    float *kv, *weff, *wtot;
    cudaGetSymbolAddress((void**)&kv,   g_kv);
    cudaGetSymbolAddress((void**)&weff, g_weff);
    cudaGetSymbolAddress((void**)&wtot, g_wtot);

    // 0) zero accumulators
    k_zero<<<132, 256>>>();

    // 1) kv = W_kv @ x   (k,v rows of w_qkv = rows 128..383)
    k_sgemm_tc<<<dim3(NPIX / 128, 2, BATCH), 256>>>(
        w_qkv + 128 * CIN, 0,
        x, (long)CIN * NPIX,
        kv, (long)256 * NPIX,
        nullptr, 256, CIN, NPIX);

    // 2) context partials (exp-softmax numerator + denominator via atomics)
    k_context<<<dim3(NPIX / TN2, HEADS, BATCH), 256>>>();

    // 3a) fold w_out with normalized context -> W_eff [b,256,128]
    k_weff<<<dim3(BATCH, 8), 256>>>(w_out);

    // 3b) W_total[b] = W_eff[b] @ W_q   (W_q = w_qkv rows 0..127, [128,256])
    k_sgemm_tc<<<dim3(2, 2, BATCH), 256>>>(
        weff, (long)256 * HID,
        w_qkv, 0,
        wtot, (long)256 * 256,
        nullptr, 256, HID, 256);

    // 4) y[b] = W_total[b] @ x[b] + b_out
    k_sgemm_tc<<<dim3(NPIX / 128, 2, BATCH), 256>>>(
        wtot, (long)256 * 256,
        x, (long)CIN * NPIX,
        out, (long)256 * NPIX,
        b_out, 256, CIN, NPIX);
}

// round 4
// speedup vs baseline: 2.5646x; 1.3998x over previous
#include <cuda_runtime.h>
#include <cuda_fp16.h>
#include <math.h>
#include <stdint.h>

#define BATCH 8
#define CIN   256
#define NPIX  16384
#define HEADS 4
#define DH    32
#define HID   128

// ---------------- scratch (device globals; no allocation allowed) ------------
__device__ float g_kv[(long)BATCH * 256 * NPIX];
__device__ float g_ctx[BATCH * HEADS * DH * DH];
__device__ float g_z[BATCH * HEADS * DH];
__device__ float g_weff[BATCH * 256 * HID];
__device__ float g_wtot[BATCH * 256 * 256];

__device__ __forceinline__ uint32_t cvt_tf32(float x) {
    uint32_t u;
    asm("cvt.rna.tf32.f32 %0, %1;" : "=r"(u) : "f"(x));
    return u;
}
__device__ __forceinline__ uint32_t smem_u32(const void* p) {
    uint32_t a;
    asm("{ .reg .u64 t; cvta.to.shared.u64 t, %1; cvt.u32.u64 %0, t; }" : "=r"(a) : "l"(p));
    return a;
}

// ---------------- zero accumulators ------------------------------------------
__global__ void k_zero() {
    int i = blockIdx.x * blockDim.x + threadIdx.x;
    if (i < BATCH * HEADS * DH * DH) g_ctx[i] = 0.f;
    if (i < BATCH * HEADS * DH)      g_z[i]   = 0.f;
}

// =============================================================================
// fp16 tensor-core batched GEMM: C[b] = A[b] @ X[b] (+bias)
// A: [M,K] row-major, X: [K,N] row-major, C: [M,N] row-major. fp32 accum.
// BM=BN=128, BK=32, 256 threads (8 warps 2x4), warp tile 64x32.
// Fragments via ldmatrix; smem padded for conflict-free LDSM.
// =============================================================================
#define LDA 40    // halves per A row (32 + 8 pad) -> 80B stride
#define LDB 136   // halves per B row (128 + 8 pad) -> 272B stride

__global__ __launch_bounds__(256, 2)
void k_hgemm(const float* __restrict__ A, long sA,
             const float* __restrict__ X, long sX,
             float* __restrict__ C, long sC,
             const float* __restrict__ bias,
             int K, int N)
{
    __shared__ __half As[128 * LDA];
    __shared__ __half Bs[32 * LDB];

    int b = blockIdx.z;
    const float* Ab = A + (long)b * sA;
    const float* Xb = X + (long)b * sX;
    float*       Cb = C + (long)b * sC;
    int m0 = blockIdx.y * 128, n0 = blockIdx.x * 128;
    int tid  = threadIdx.x;
    int wid  = tid >> 5, lane = tid & 31;
    int g4   = lane >> 2, q = lane & 3;
    int wm   = (wid >> 2) * 64;     // 0 or 64
    int wn   = (wid & 3) * 32;      // 0,32,64,96

    uint32_t sbA = smem_u32(As), sbB = smem_u32(Bs);
    // ldmatrix lane -> (row-within-16, col-sel) mapping (same for A and B.trans)
    int rowoff = (lane & 7) + ((lane >> 3) & 1) * 8;
    int colsel = (lane >> 4) * 8;

    float acc[4][4][4];
#pragma unroll
    for (int i = 0; i < 4; i++)
#pragma unroll
        for (int j = 0; j < 4; j++)
#pragma unroll
            for (int r = 0; r < 4; r++) acc[i][j][r] = 0.f;

    for (int k0 = 0; k0 < K; k0 += 32) {
        // ---- A tile: 128 rows x 32 k, f32->f16, natural [m][k] layout
#pragma unroll
        for (int i = 0; i < 4; i++) {
            int f  = i * 256 + tid;
            int m  = f >> 3, k4 = (f & 7) << 2;
            float4 v = *(const float4*)&Ab[(long)(m0 + m) * K + k0 + k4];
            __half2 h0 = __floats2half2_rn(v.x, v.y);
            __half2 h1 = __floats2half2_rn(v.z, v.w);
            uint2 u = { *(uint32_t*)&h0, *(uint32_t*)&h1 };
            *(uint2*)&As[m * LDA + k4] = u;
        }
        // ---- B tile: 32 k x 128 n, f32->f16, natural [k][n] layout
#pragma unroll
        for (int i = 0; i < 4; i++) {
            int f  = i * 256 + tid;
            int kk = f >> 5, n4 = (f & 31) << 2;
            float4 v = *(const float4*)&Xb[(long)(k0 + kk) * N + n0 + n4];
            __half2 h0 = __floats2half2_rn(v.x, v.y);
            __half2 h1 = __floats2half2_rn(v.z, v.w);
            uint2 u = { *(uint32_t*)&h0, *(uint32_t*)&h1 };
            *(uint2*)&Bs[kk * LDB + n4] = u;
        }
        __syncthreads();

#pragma unroll
        for (int ks = 0; ks < 32; ks += 16) {
            uint32_t af[4][4];
#pragma unroll
            for (int mf = 0; mf < 4; mf++) {
                uint32_t addr = sbA + (uint32_t)(((wm + mf * 16 + rowoff) * LDA
                                                  + ks + colsel) * 2);
                asm volatile(
                    "ldmatrix.sync.aligned.m8n8.x4.shared.b16 {%0,%1,%2,%3}, [%4];"
                    : "=r"(af[mf][0]), "=r"(af[mf][1]), "=r"(af[mf][2]), "=r"(af[mf][3])
                    : "r"(addr));
            }
            uint32_t bf[2][4];
#pragma unroll
            for (int np = 0; np < 2; np++) {
                uint32_t addr = sbB + (uint32_t)(((ks + rowoff) * LDB
                                                  + wn + np * 16 + colsel) * 2);
                asm volatile(
                    "ldmatrix.sync.aligned.m8n8.x4.trans.shared.b16 {%0,%1,%2,%3}, [%4];"
                    : "=r"(bf[np][0]), "=r"(bf[np][1]), "=r"(bf[np][2]), "=r"(bf[np][3])
                    : "r"(addr));
            }
#pragma unroll
            for (int nf = 0; nf < 4; nf++) {
                uint32_t b0 = bf[nf >> 1][(nf & 1) * 2];
                uint32_t b1 = bf[nf >> 1][(nf & 1) * 2 + 1];
#pragma unroll
                for (int mf = 0; mf < 4; mf++) {
                    asm volatile(
                        "mma.sync.aligned.m16n8k16.row.col.f32.f16.f16.f32 "
                        "{%0,%1,%2,%3},{%4,%5,%6,%7},{%8,%9},{%0,%1,%2,%3};"
                        : "+f"(acc[mf][nf][0]), "+f"(acc[mf][nf][1]),
                          "+f"(acc[mf][nf][2]), "+f"(acc[mf][nf][3])
                        : "r"(af[mf][0]), "r"(af[mf][1]),
                          "r"(af[mf][2]), "r"(af[mf][3]),
                          "r"(b0), "r"(b1));
                }
            }
        }
        __syncthreads();
    }

    // ---- epilogue: c0,c1 at (row, 2q..2q+1); c2,c3 at row+8
#pragma unroll
    for (int mf = 0; mf < 4; mf++) {
        int mrow = m0 + wm + mf * 16 + g4;
        float bv0 = bias ? bias[mrow]     : 0.f;
        float bv1 = bias ? bias[mrow + 8] : 0.f;
#pragma unroll
        for (int nf = 0; nf < 4; nf++) {
            int nc = n0 + wn + nf * 8 + 2 * q;
            float2 v0 = { acc[mf][nf][0] + bv0, acc[mf][nf][1] + bv0 };
            float2 v1 = { acc[mf][nf][2] + bv1, acc[mf][nf][3] + bv1 };
            *(float2*)&Cb[(long)mrow * N + nc]       = v0;
            *(float2*)&Cb[(long)(mrow + 8) * N + nc] = v1;
        }
    }
}

// ---------------- tf32 mma.sync SGEMM (tiny fold GEMM only) ------------------
__global__ __launch_bounds__(256, 2)
void k_sgemm_tc(const float* __restrict__ A, long sA,
                const float* __restrict__ X, long sX,
                float* __restrict__ C, long sC,
                const float* __restrict__ bias,
                int M, int K, int N)
{
    const int BM = 128, BN = 128, BK = 32;
    __shared__ uint32_t As[BK][BM + 4];
    __shared__ uint32_t Bs[BK][BN + 4];

    int b = blockIdx.z;
    const float* Ab = A + (long)b * sA;
    const float* Xb = X + (long)b * sX;
    float*       Cb = C + (long)b * sC;
    int m0 = blockIdx.y * BM, n0 = blockIdx.x * BN;
    int tid  = threadIdx.x;
    int wid  = tid >> 5, lane = tid & 31;
    int g4   = lane >> 2, q = lane & 3;
    int wm   = (wid >> 2) * 64;
    int wn   = (wid & 3) * 32;

    float acc[4][4][4];
#pragma unroll
    for (int i = 0; i < 4; i++)
#pragma unroll
        for (int j = 0; j < 4; j++)
#pragma unroll
            for (int r = 0; r < 4; r++) acc[i][j][r] = 0.f;

    for (int k0 = 0; k0 < K; k0 += BK) {
#pragma unroll
        for (int i = 0; i < 4; i++) {
            int f  = i * 256 + tid;
            int m  = f >> 3, k4 = (f & 7) << 2;
            float4 v = *(const float4*)&Ab[(long)(m0 + m) * K + k0 + k4];
            As[k4 + 0][m] = cvt_tf32(v.x); As[k4 + 1][m] = cvt_tf32(v.y);
            As[k4 + 2][m] = cvt_tf32(v.z); As[k4 + 3][m] = cvt_tf32(v.w);
        }
#pragma unroll
        for (int i = 0; i < 4; i++) {
            int f  = i * 256 + tid;
            int kk = f >> 5, n4 = (f & 31) << 2;
            float4 v = *(const float4*)&Xb[(long)(k0 + kk) * N + n0 + n4];
            uint4 u;
            u.x = cvt_tf32(v.x); u.y = cvt_tf32(v.y);
            u.z = cvt_tf32(v.z); u.w = cvt_tf32(v.w);
            *(uint4*)&Bs[kk][n4] = u;
        }
        __syncthreads();

#pragma unroll
        for (int ks = 0; ks < BK; ks += 8) {
            uint32_t af[4][4];
#pragma unroll
            for (int mf = 0; mf < 4; mf++) {
                int mb = wm + mf * 16;
                af[mf][0] = As[ks + q    ][mb + g4    ];
                af[mf][1] = As[ks + q    ][mb + g4 + 8];
                af[mf][2] = As[ks + q + 4][mb + g4    ];
                af[mf][3] = As[ks + q + 4][mb + g4 + 8];
            }
#pragma unroll
            for (int nf = 0; nf < 4; nf++) {
                int nb = wn + nf * 8;
                uint32_t b0 = Bs[ks + q    ][nb + g4];
                uint32_t b1 = Bs[ks + q + 4][nb + g4];
#pragma unroll
                for (int mf = 0; mf < 4; mf++) {
                    asm volatile(
                        "mma.sync.aligned.m16n8k8.row.col.f32.tf32.tf32.f32 "
                        "{%0,%1,%2,%3},{%4,%5,%6,%7},{%8,%9},{%0,%1,%2,%3};"
                        : "+f"(acc[mf][nf][0]), "+f"(acc[mf][nf][1]),
                          "+f"(acc[mf][nf][2]), "+f"(acc[mf][nf][3])
                        : "r"(af[mf][0]), "r"(af[mf][1]),
                          "r"(af[mf][2]), "r"(af[mf][3]),
                          "r"(b0), "r"(b1));
                }
            }
        }
        __syncthreads();
    }

#pragma unroll
    for (int mf = 0; mf < 4; mf++) {
        int mrow = m0 + wm + mf * 16 + g4;
        float bv0 = bias ? bias[mrow]     : 0.f;
        float bv1 = bias ? bias[mrow + 8] : 0.f;
#pragma unroll
        for (int nf = 0; nf < 4; nf++) {
            int nc = n0 + wn + nf * 8 + 2 * q;
            float2 v0 = { acc[mf][nf][0] + bv0, acc[mf][nf][1] + bv0 };
            float2 v1 = { acc[mf][nf][2] + bv1, acc[mf][nf][3] + bv1 };
            *(float2*)&Cb[(long)mrow * N + nc]       = v0;
            *(float2*)&Cb[(long)(mrow + 8) * N + nc] = v1;
        }
    }
}

// ---------------- context partials: ctx[d,e] += sum_n exp(k[d,n]) v[e,n] -----
#define TN2 128
__global__ __launch_bounds__(256)
void k_context()
{
    __shared__ float ek[32][TN2 + 1];
    __shared__ float vs[32][TN2 + 1];
    int b = blockIdx.z, h = blockIdx.y;
    long n0 = (long)blockIdx.x * TN2;
    const float* kb = g_kv + ((long)b * 256 + h * 32) * NPIX + n0;
    const float* vb = g_kv + ((long)b * 256 + 128 + h * 32) * NPIX + n0;
    int tid = threadIdx.x;

    int row = tid >> 3;
    int c0 = (tid & 7) << 4;
    float zp = 0.f;
#pragma unroll
    for (int c = 0; c < 16; c += 4) {
        float4 kk = *(const float4*)&kb[(long)row * NPIX + c0 + c];
        float e0 = expf(kk.x), e1 = expf(kk.y), e2 = expf(kk.z), e3 = expf(kk.w);
        ek[row][c0 + c + 0] = e0; ek[row][c0 + c + 1] = e1;
        ek[row][c0 + c + 2] = e2; ek[row][c0 + c + 3] = e3;
        zp += (e0 + e1) + (e2 + e3);
        float4 vv = *(const float4*)&vb[(long)row * NPIX + c0 + c];
        vs[row][c0 + c + 0] = vv.x; vs[row][c0 + c + 1] = vv.y;
        vs[row][c0 + c + 2] = vv.z; vs[row][c0 + c + 3] = vv.w;
    }
    atomicAdd(&g_z[(b * HEADS + h) * DH + row], zp);
    __syncthreads();

    int g  = tid >> 6;
    int tg = tid & 63;
    int td = (tg >> 3) << 2;
    int te = (tg & 7)  << 2;
    int nb = g << 5;
    float acc[4][4];
#pragma unroll
    for (int i = 0; i < 4; i++)
#pragma unroll
        for (int j = 0; j < 4; j++) acc[i][j] = 0.f;

#pragma unroll 4
    for (int n = 0; n < 32; n++) {
        float a0 = ek[td + 0][nb + n], a1 = ek[td + 1][nb + n];
        float a2 = ek[td + 2][nb + n], a3 = ek[td + 3][nb + n];
        float b0 = vs[te + 0][nb + n], b1 = vs[te + 1][nb + n];
        float b2 = vs[te + 2][nb + n], b3 = vs[te + 3][nb + n];
        acc[0][0] = fmaf(a0, b0, acc[0][0]); acc[0][1] = fmaf(a0, b1, acc[0][1]);
        acc[0][2] = fmaf(a0, b2, acc[0][2]); acc[0][3] = fmaf(a0, b3, acc[0][3]);
        acc[1][0] = fmaf(a1, b0, acc[1][0]); acc[1][1] = fmaf(a1, b1, acc[1][1]);
        acc[1][2] = fmaf(a1, b2, acc[1][2]); acc[1][3] = fmaf(a1, b3, acc[1][3]);
        acc[2][0] = fmaf(a2, b0, acc[2][0]); acc[2][1] = fmaf(a2, b1, acc[2][1]);
        acc[2][2] = fmaf(a2, b2, acc[2][2]); acc[2][3] = fmaf(a2, b3, acc[2][3]);
        acc[3][0] = fmaf(a3, b0, acc[3][0]); acc[3][1] = fmaf(a3, b1, acc[3][1]);
        acc[3][2] = fmaf(a3, b2, acc[3][2]); acc[3][3] = fmaf(a3, b3, acc[3][3]);
    }
    float* cp = g_ctx + (long)(b * HEADS + h) * DH * DH;
#pragma unroll
    for (int i = 0; i < 4; i++)
#pragma unroll
        for (int j = 0; j < 4; j++)
            atomicAdd(&cp[(td + i) * DH + te + j], acc[i][j]);
}

// ---------------- fold: W_eff[b][o][h*32+d] = sum_e w_out[o][h*32+e]*ctxn[h][d][e]
__global__ __launch_bounds__(256)
void k_weff(const float* __restrict__ w_out)
{
    __shared__ float ctxn[HEADS][DH][DH + 1];
    __shared__ float zinv[HEADS * DH];
    int b = blockIdx.x, oc = blockIdx.y;   // oc in 0..31, 8 o-rows each
    int tid = threadIdx.x;
    if (tid < 128) zinv[tid] = 1.0f / g_z[b * 128 + tid];
    __syncthreads();
    for (int i = tid; i < 4096; i += 256) {
        int h = i >> 10, d = (i >> 5) & 31, e = i & 31;
        ctxn[h][d][e] = g_ctx[b * 4096 + i] * zinv[h * 32 + d];
    }
    __syncthreads();
    for (int i = tid; i < 8 * 128; i += 256) {
        int ol = i >> 7;
        int hd = i & 127;
        int h = hd >> 5, d = hd & 31;
        int o = oc * 8 + ol;
        const float* wrow = w_out + o * HID + h * 32;
        float s = 0.f;
#pragma unroll
        for (int e = 0; e < 32; e++) s = fmaf(wrow[e], ctxn[h][d][e], s);
        g_weff[((long)b * 256 + o) * HID + hd] = s;
    }
}

// ---------------- launch --------------------------------------------------
extern "C" void kernel_launch(void* const* d_in, const int* in_sizes, int n_in,
                              void* d_out, int out_size)
{
    const float *x = nullptr, *w_qkv = nullptr, *w_out = nullptr, *b_out = nullptr;
    for (int i = 0; i < n_in; i++) {
        const float* p = (const float*)d_in[i];
        if      (in_sizes[i] == BATCH * CIN * NPIX) x     = p;
        else if (in_sizes[i] == 3 * HID * CIN)      w_qkv = p;
        else if (in_sizes[i] == CIN * HID)          w_out = p;
        else if (in_sizes[i] == CIN)                b_out = p;
    }
    float* out = (float*)d_out;

    float *kv, *weff, *wtot;
    cudaGetSymbolAddress((void**)&kv,   g_kv);
    cudaGetSymbolAddress((void**)&weff, g_weff);
    cudaGetSymbolAddress((void**)&wtot, g_wtot);

    // 0) zero accumulators
    k_zero<<<132, 256>>>();

    // 1) kv = W_kv @ x (fp16 mma): rows 128..383 of w_qkv = k,v weights
    k_hgemm<<<dim3(NPIX / 128, 2, BATCH), 256>>>(
        w_qkv + 128 * CIN, 0,
        x, (long)CIN * NPIX,
        kv, (long)256 * NPIX,
        nullptr, CIN, NPIX);

    // 2) context partials
    k_context<<<dim3(NPIX / TN2, HEADS, BATCH), 256>>>();

    // 3a) fold w_out with normalized context -> W_eff
    k_weff<<<dim3(BATCH, 32), 256>>>(w_out);

    // 3b) W_total[b] = W_eff[b] @ W_q  (tiny, tf32 path)
    k_sgemm_tc<<<dim3(2, 2, BATCH), 256>>>(
        weff, (long)256 * HID,
        w_qkv, 0,
        wtot, (long)256 * 256,
        nullptr, 256, HID, 256);

    // 4) y[b] = W_total[b] @ x[b] + b_out (fp16 mma)
    k_hgemm<<<dim3(NPIX / 128, 2, BATCH), 256>>>(
        wtot, (long)256 * 256,
        x, (long)CIN * NPIX,
        out, (long)256 * NPIX,
        b_out, CIN, NPIX);
}

// round 5
// speedup vs baseline: 3.5407x; 1.3806x over previous
#include <cuda_runtime.h>
#include <cuda_fp16.h>
#include <math.h>
#include <stdint.h>

#define BATCH 8
#define CIN   256
#define NPIX  16384
#define HEADS 4
#define DH    32
#define HID   128

// ---------------- scratch (device globals; no allocation allowed) ------------
__device__ __half g_xh[(long)BATCH * CIN * NPIX];     // x in fp16
__device__ __half g_kvh[(long)BATCH * 256 * NPIX];    // k rows 0..127, v rows 128..255 (fp16)
__device__ __half g_wh[256 * 256];                    // W_kv in fp16
__device__ __half g_wtoth[BATCH * 256 * 256];         // per-batch effective weight (fp16)
__device__ float  g_ctx[BATCH * HEADS * DH * DH];
__device__ float  g_z[BATCH * HEADS * DH];
__device__ float  g_weff[BATCH * 256 * HID];

__device__ __forceinline__ uint32_t cvt_tf32(float x) {
    uint32_t u;
    asm("cvt.rna.tf32.f32 %0, %1;" : "=r"(u) : "f"(x));
    return u;
}
__device__ __forceinline__ uint32_t smem_u32(const void* p) {
    uint32_t a;
    asm("{ .reg .u64 t; cvta.to.shared.u64 t, %1; cvt.u32.u64 %0, t; }" : "=r"(a) : "l"(p));
    return a;
}
#define CP16(dst, src) \
    asm volatile("cp.async.cg.shared.global [%0], [%1], 16;" :: "r"(dst), "l"(src) : "memory")

// ---------------- zero accumulators ------------------------------------------
__global__ void k_zero() {
    int i = blockIdx.x * blockDim.x + threadIdx.x;
    if (i < BATCH * HEADS * DH * DH) g_ctx[i] = 0.f;
    if (i < BATCH * HEADS * DH)      g_z[i]   = 0.f;
}

// ---------------- fp32 -> fp16 pre-convert (x and W_kv) ----------------------
__global__ void k_cvt(const float* __restrict__ x, const float* __restrict__ wkv) {
    long i = (long)blockIdx.x * blockDim.x + threadIdx.x;
    if (i < 16384) {   // W_kv: 65536 elems = 16384 float4
        float4 v = ((const float4*)wkv)[i];
        __half2 h0 = __floats2half2_rn(v.x, v.y);
        __half2 h1 = __floats2half2_rn(v.z, v.w);
        uint2 u = { *(uint32_t*)&h0, *(uint32_t*)&h1 };
        ((uint2*)g_wh)[i] = u;
    }
    long stride = (long)gridDim.x * blockDim.x;
    for (long f = i; f < (long)BATCH * CIN * NPIX / 4; f += stride) {
        float4 v = ((const float4*)x)[f];
        __half2 h0 = __floats2half2_rn(v.x, v.y);
        __half2 h1 = __floats2half2_rn(v.z, v.w);
        uint2 u = { *(uint32_t*)&h0, *(uint32_t*)&h1 };
        ((uint2*)g_xh)[f] = u;
    }
}

// =============================================================================
// fp16 cp.async-pipelined GEMM: C[b] = A[b] @ X[b] (+bias)
// A: fp16 [M>=128 rows, K=256] row-major. X: fp16 [256, NPIX]. C: [*, NPIX].
// BM=128, BN=128, BK=64, 2-stage cp.async double buffer, 256 thr (8 warps 2x4),
// warp tile 64x32, ldmatrix fragment feeds, fp32 accum.
// =============================================================================
#define LDA 72    // halves per A smem row (64 + 8 pad) -> 144B
#define LDB 136   // halves per B smem row (128 + 8 pad) -> 272B
#define A_BUF 18432   // 128*144
#define B_BUF 17408   // 64*272
#define SMEM_G (2 * A_BUF + 2 * B_BUF)   // 71680

__device__ __forceinline__ void g2s_tile(uint32_t sb, int buf,
                                         const __half* Arow, const __half* Xb,
                                         long n0, int k0) {
    int tid = threadIdx.x;
    uint32_t abase = sb + buf * A_BUF;
    uint32_t bbase = sb + 2 * A_BUF + buf * B_BUF;
#pragma unroll
    for (int i = 0; i < 4; i++) {          // A: 128 rows x 64k = 1024 x 16B
        int f = i * 256 + tid;
        int r = f >> 3, c = f & 7;
        CP16(abase + r * 144 + c * 16, Arow + (long)r * 256 + k0 + c * 8);
    }
#pragma unroll
    for (int i = 0; i < 4; i++) {          // B: 64 rows x 128n = 1024 x 16B
        int f = i * 256 + tid;
        int r = f >> 4, c = f & 15;
        CP16(bbase + r * 272 + c * 16, Xb + (long)(k0 + r) * NPIX + n0 + c * 8);
    }
    asm volatile("cp.async.commit_group;" ::: "memory");
}

__global__ __launch_bounds__(256, 2)
void k_hgemm_async(const __half* __restrict__ A, long sA,
                   const __half* __restrict__ X, long sX,
                   void* __restrict__ Cv, long sC,
                   const float* __restrict__ bias, int half_out)
{
    extern __shared__ char smem[];
    uint32_t sb = smem_u32(smem);

    int b = blockIdx.z;
    const __half* Ab = A + (long)b * sA + (long)blockIdx.y * 128 * 256;
    const __half* Xb = X + (long)b * sX;
    long n0 = (long)blockIdx.x * 128;
    int m0 = blockIdx.y * 128;

    int tid  = threadIdx.x;
    int wid  = tid >> 5, lane = tid & 31;
    int g4   = lane >> 2, q = lane & 3;
    int wm   = (wid >> 2) * 64;
    int wn   = (wid & 3) * 32;
    int rowoff = (lane & 7) + ((lane >> 3) & 1) * 8;
    int colsel = (lane >> 4) * 8;

    float acc[4][4][4];
#pragma unroll
    for (int i = 0; i < 4; i++)
#pragma unroll
        for (int j = 0; j < 4; j++)
#pragma unroll
            for (int r = 0; r < 4; r++) acc[i][j][r] = 0.f;

    g2s_tile(sb, 0, Ab, Xb, n0, 0);

#pragma unroll 1
    for (int t = 0; t < 4; t++) {
        if (t < 3) g2s_tile(sb, (t + 1) & 1, Ab, Xb, n0, (t + 1) * 64);
        if (t < 3) { asm volatile("cp.async.wait_group 1;" ::: "memory"); }
        else       { asm volatile("cp.async.wait_group 0;" ::: "memory"); }
        __syncthreads();

        uint32_t abase = sb + (t & 1) * A_BUF;
        uint32_t bbase = sb + 2 * A_BUF + (t & 1) * B_BUF;
#pragma unroll
        for (int ks = 0; ks < 64; ks += 16) {
            uint32_t af[4][4];
#pragma unroll
            for (int mf = 0; mf < 4; mf++) {
                uint32_t addr = abase + (uint32_t)((wm + mf * 16 + rowoff) * 144
                                                   + (ks + colsel) * 2);
                asm volatile(
                    "ldmatrix.sync.aligned.m8n8.x4.shared.b16 {%0,%1,%2,%3}, [%4];"
                    : "=r"(af[mf][0]), "=r"(af[mf][1]), "=r"(af[mf][2]), "=r"(af[mf][3])
                    : "r"(addr));
            }
            uint32_t bf[2][4];
#pragma unroll
            for (int np = 0; np < 2; np++) {
                uint32_t addr = bbase + (uint32_t)((ks + rowoff) * 272
                                                   + (wn + np * 16 + colsel) * 2);
                asm volatile(
                    "ldmatrix.sync.aligned.m8n8.x4.trans.shared.b16 {%0,%1,%2,%3}, [%4];"
                    : "=r"(bf[np][0]), "=r"(bf[np][1]), "=r"(bf[np][2]), "=r"(bf[np][3])
                    : "r"(addr));
            }
#pragma unroll
            for (int nf = 0; nf < 4; nf++) {
                uint32_t b0 = bf[nf >> 1][(nf & 1) * 2];
                uint32_t b1 = bf[nf >> 1][(nf & 1) * 2 + 1];
#pragma unroll
                for (int mf = 0; mf < 4; mf++) {
                    asm volatile(
                        "mma.sync.aligned.m16n8k16.row.col.f32.f16.f16.f32 "
                        "{%0,%1,%2,%3},{%4,%5,%6,%7},{%8,%9},{%0,%1,%2,%3};"
                        : "+f"(acc[mf][nf][0]), "+f"(acc[mf][nf][1]),
                          "+f"(acc[mf][nf][2]), "+f"(acc[mf][nf][3])
                        : "r"(af[mf][0]), "r"(af[mf][1]),
                          "r"(af[mf][2]), "r"(af[mf][3]),
                          "r"(b0), "r"(b1));
                }
            }
        }
        __syncthreads();
    }

    // ---- epilogue
    if (half_out) {
        __half* Ch = (__half*)Cv + (long)b * sC;
#pragma unroll
        for (int mf = 0; mf < 4; mf++) {
            long mrow = m0 + wm + mf * 16 + g4;
#pragma unroll
            for (int nf = 0; nf < 4; nf++) {
                long nc = n0 + wn + nf * 8 + 2 * q;
                *(__half2*)&Ch[mrow * NPIX + nc] =
                    __floats2half2_rn(acc[mf][nf][0], acc[mf][nf][1]);
                *(__half2*)&Ch[(mrow + 8) * NPIX + nc] =
                    __floats2half2_rn(acc[mf][nf][2], acc[mf][nf][3]);
            }
        }
    } else {
        float* Cf = (float*)Cv + (long)b * sC;
#pragma unroll
        for (int mf = 0; mf < 4; mf++) {
            long mrow = m0 + wm + mf * 16 + g4;
            float bv0 = bias ? bias[mrow]     : 0.f;
            float bv1 = bias ? bias[mrow + 8] : 0.f;
#pragma unroll
            for (int nf = 0; nf < 4; nf++) {
                long nc = n0 + wn + nf * 8 + 2 * q;
                float2 v0 = { acc[mf][nf][0] + bv0, acc[mf][nf][1] + bv0 };
                float2 v1 = { acc[mf][nf][2] + bv1, acc[mf][nf][3] + bv1 };
                *(float2*)&Cf[mrow * NPIX + nc]       = v0;
                *(float2*)&Cf[(mrow + 8) * NPIX + nc] = v1;
            }
        }
    }
}

// ---------------- tf32 mma SGEMM -> fp16 out (tiny fold GEMM) ----------------
__global__ __launch_bounds__(256, 2)
void k_sgemm_tc(const float* __restrict__ A, long sA,
                const float* __restrict__ X, long sX,
                __half* __restrict__ C, long sC,
                int M, int K, int N)
{
    const int BM = 128, BN = 128, BK = 32;
    __shared__ uint32_t As[BK][BM + 4];
    __shared__ uint32_t Bs[BK][BN + 4];

    int b = blockIdx.z;
    const float* Ab = A + (long)b * sA;
    const float* Xb = X + (long)b * sX;
    __half*      Cb = C + (long)b * sC;
    int m0 = blockIdx.y * BM, n0 = blockIdx.x * BN;
    int tid  = threadIdx.x;
    int wid  = tid >> 5, lane = tid & 31;
    int g4   = lane >> 2, q = lane & 3;
    int wm   = (wid >> 2) * 64;
    int wn   = (wid & 3) * 32;

    float acc[4][4][4];
#pragma unroll
    for (int i = 0; i < 4; i++)
#pragma unroll
        for (int j = 0; j < 4; j++)
#pragma unroll
            for (int r = 0; r < 4; r++) acc[i][j][r] = 0.f;

    for (int k0 = 0; k0 < K; k0 += BK) {
#pragma unroll
        for (int i = 0; i < 4; i++) {
            int f  = i * 256 + tid;
            int m  = f >> 3, k4 = (f & 7) << 2;
            float4 v = *(const float4*)&Ab[(long)(m0 + m) * K + k0 + k4];
            As[k4 + 0][m] = cvt_tf32(v.x); As[k4 + 1][m] = cvt_tf32(v.y);
            As[k4 + 2][m] = cvt_tf32(v.z); As[k4 + 3][m] = cvt_tf32(v.w);
        }
#pragma unroll
        for (int i = 0; i < 4; i++) {
            int f  = i * 256 + tid;
            int kk = f >> 5, n4 = (f & 31) << 2;
            float4 v = *(const float4*)&Xb[(long)(k0 + kk) * N + n0 + n4];
            uint4 u;
            u.x = cvt_tf32(v.x); u.y = cvt_tf32(v.y);
            u.z = cvt_tf32(v.z); u.w = cvt_tf32(v.w);
            *(uint4*)&Bs[kk][n4] = u;
        }
        __syncthreads();

#pragma unroll
        for (int ks = 0; ks < BK; ks += 8) {
            uint32_t af[4][4];
#pragma unroll
            for (int mf = 0; mf < 4; mf++) {
                int mb = wm + mf * 16;
                af[mf][0] = As[ks + q    ][mb + g4    ];
                af[mf][1] = As[ks + q    ][mb + g4 + 8];
                af[mf][2] = As[ks + q + 4][mb + g4    ];
                af[mf][3] = As[ks + q + 4][mb + g4 + 8];
            }
#pragma unroll
            for (int nf = 0; nf < 4; nf++) {
                int nb = wn + nf * 8;
                uint32_t b0 = Bs[ks + q    ][nb + g4];
                uint32_t b1 = Bs[ks + q + 4][nb + g4];
#pragma unroll
                for (int mf = 0; mf < 4; mf++) {
                    asm volatile(
                        "mma.sync.aligned.m16n8k8.row.col.f32.tf32.tf32.f32 "
                        "{%0,%1,%2,%3},{%4,%5,%6,%7},{%8,%9},{%0,%1,%2,%3};"
                        : "+f"(acc[mf][nf][0]), "+f"(acc[mf][nf][1]),
                          "+f"(acc[mf][nf][2]), "+f"(acc[mf][nf][3])
                        : "r"(af[mf][0]), "r"(af[mf][1]),
                          "r"(af[mf][2]), "r"(af[mf][3]),
                          "r"(b0), "r"(b1));
                }
            }
        }
        __syncthreads();
    }

#pragma unroll
    for (int mf = 0; mf < 4; mf++) {
        int mrow = m0 + wm + mf * 16 + g4;
#pragma unroll
        for (int nf = 0; nf < 4; nf++) {
            int nc = n0 + wn + nf * 8 + 2 * q;
            *(__half2*)&Cb[(long)mrow * N + nc] =
                __floats2half2_rn(acc[mf][nf][0], acc[mf][nf][1]);
            *(__half2*)&Cb[(long)(mrow + 8) * N + nc] =
                __floats2half2_rn(acc[mf][nf][2], acc[mf][nf][3]);
        }
    }
}

// ---------------- context: ctx[d,e] += sum_n exp(k[d,n]) v[e,n] (fp16 kv) ----
// grid (NPIX/512, HEADS, BATCH) = (32,4,8); 4 subtiles of 128 px per block.
__global__ __launch_bounds__(256)
void k_context()
{
    __shared__ float ek[32][132];
    __shared__ float vs[32][132];
    __shared__ float zs[32];
    int b = blockIdx.z, h = blockIdx.y;
    long n0 = (long)blockIdx.x * 512;
    const __half* kb = g_kvh + ((long)b * 256 + h * 32) * NPIX + n0;
    const __half* vb = g_kvh + ((long)b * 256 + 128 + h * 32) * NPIX + n0;
    int tid = threadIdx.x;
    int row = tid >> 3;
    int c0 = (tid & 7) << 4;

    int g  = tid >> 6;
    int tg = tid & 63;
    int td = (tg >> 3) << 2;
    int te = (tg & 7)  << 2;
    int nb = g << 5;

    if (tid < 32) zs[tid] = 0.f;
    float zp = 0.f;
    float acc[4][4];
#pragma unroll
    for (int i = 0; i < 4; i++)
#pragma unroll
        for (int j = 0; j < 4; j++) acc[i][j] = 0.f;

#pragma unroll 1
    for (int sub = 0; sub < 4; sub++) {
        long base = (long)row * NPIX + sub * 128 + c0;
        // k: 16 halves -> exp -> ek
        {
            uint4 u0 = *(const uint4*)&kb[base];
            uint4 u1 = *(const uint4*)&kb[base + 8];
            const __half2* hp0 = (const __half2*)&u0;
            const __half2* hp1 = (const __half2*)&u1;
#pragma unroll
            for (int j = 0; j < 4; j++) {
                float2 f0 = __half22float2(hp0[j]);
                float2 f1 = __half22float2(hp1[j]);
                float e0 = expf(f0.x), e1 = expf(f0.y);
                float e2 = expf(f1.x), e3 = expf(f1.y);
                ek[row][c0 + 2 * j]     = e0;
                ek[row][c0 + 2 * j + 1] = e1;
                ek[row][c0 + 8 + 2 * j]     = e2;
                ek[row][c0 + 8 + 2 * j + 1] = e3;
                zp += (e0 + e1) + (e2 + e3);
            }
        }
        // v: 16 halves -> vs
        {
            uint4 u0 = *(const uint4*)&vb[base];
            uint4 u1 = *(const uint4*)&vb[base + 8];
            const __half2* hp0 = (const __half2*)&u0;
            const __half2* hp1 = (const __half2*)&u1;
#pragma unroll
            for (int j = 0; j < 4; j++) {
                float2 f0 = __half22float2(hp0[j]);
                float2 f1 = __half22float2(hp1[j]);
                vs[row][c0 + 2 * j]         = f0.x;
                vs[row][c0 + 2 * j + 1]     = f0.y;
                vs[row][c0 + 8 + 2 * j]     = f1.x;
                vs[row][c0 + 8 + 2 * j + 1] = f1.y;
            }
        }
        __syncthreads();

#pragma unroll 4
        for (int n = 0; n < 32; n++) {
            float a0 = ek[td + 0][nb + n], a1 = ek[td + 1][nb + n];
            float a2 = ek[td + 2][nb + n], a3 = ek[td + 3][nb + n];
            float b0 = vs[te + 0][nb + n], b1 = vs[te + 1][nb + n];
            float b2 = vs[te + 2][nb + n], b3 = vs[te + 3][nb + n];
            acc[0][0] = fmaf(a0, b0, acc[0][0]); acc[0][1] = fmaf(a0, b1, acc[0][1]);
            acc[0][2] = fmaf(a0, b2, acc[0][2]); acc[0][3] = fmaf(a0, b3, acc[0][3]);
            acc[1][0] = fmaf(a1, b0, acc[1][0]); acc[1][1] = fmaf(a1, b1, acc[1][1]);
            acc[1][2] = fmaf(a1, b2, acc[1][2]); acc[1][3] = fmaf(a1, b3, acc[1][3]);
            acc[2][0] = fmaf(a2, b0, acc[2][0]); acc[2][1] = fmaf(a2, b1, acc[2][1]);
            acc[2][2] = fmaf(a2, b2, acc[2][2]); acc[2][3] = fmaf(a2, b3, acc[2][3]);
            acc[3][0] = fmaf(a3, b0, acc[3][0]); acc[3][1] = fmaf(a3, b1, acc[3][1]);
            acc[3][2] = fmaf(a3, b2, acc[3][2]); acc[3][3] = fmaf(a3, b3, acc[3][3]);
        }
        __syncthreads();
    }

    // z: smem reduce (8 threads/row) then 32 global atomics per block
    atomicAdd(&zs[row], zp);
    __syncthreads();
    if (tid < 32) atomicAdd(&g_z[(b * HEADS + h) * DH + tid], zs[tid]);

    // ctx: 16 global atomics per thread (spread addresses, 1M total on grid)
    float* cp = g_ctx + (long)(b * HEADS + h) * DH * DH;
#pragma unroll
    for (int i = 0; i < 4; i++)
#pragma unroll
        for (int j = 0; j < 4; j++)
            atomicAdd(&cp[(td + i) * DH + te + j], acc[i][j]);
}

// ---------------- fold: W_eff[b][o][h*32+d] = sum_e w_out[o][h*32+e]*ctxn[h][d][e]
__global__ __launch_bounds__(256)
void k_weff(const float* __restrict__ w_out)
{
    __shared__ float ctxn[HEADS][DH][DH + 1];
    __shared__ float zinv[HEADS * DH];
    int b = blockIdx.x, oc = blockIdx.y;
    int tid = threadIdx.x;
    if (tid < 128) zinv[tid] = 1.0f / g_z[b * 128 + tid];
    __syncthreads();
    for (int i = tid; i < 4096; i += 256) {
        int h = i >> 10, d = (i >> 5) & 31, e = i & 31;
        ctxn[h][d][e] = g_ctx[b * 4096 + i] * zinv[h * 32 + d];
    }
    __syncthreads();
    for (int i = tid; i < 8 * 128; i += 256) {
        int ol = i >> 7;
        int hd = i & 127;
        int h = hd >> 5, d = hd & 31;
        int o = oc * 8 + ol;
        const float* wrow = w_out + o * HID + h * 32;
        float s = 0.f;
#pragma unroll
        for (int e = 0; e < 32; e++) s = fmaf(wrow[e], ctxn[h][d][e], s);
        g_weff[((long)b * 256 + o) * HID + hd] = s;
    }
}

// ---------------- launch --------------------------------------------------
extern "C" void kernel_launch(void* const* d_in, const int* in_sizes, int n_in,
                              void* d_out, int out_size)
{
    const float *x = nullptr, *w_qkv = nullptr, *w_out = nullptr, *b_out = nullptr;
    for (int i = 0; i < n_in; i++) {
        const float* p = (const float*)d_in[i];
        if      (in_sizes[i] == BATCH * CIN * NPIX) x     = p;
        else if (in_sizes[i] == 3 * HID * CIN)      w_qkv = p;
        else if (in_sizes[i] == CIN * HID)          w_out = p;
        else if (in_sizes[i] == CIN)                b_out = p;
    }
    float* out = (float*)d_out;

    __half *xh, *kvh, *wh, *wtoth;
    float *weff;
    cudaGetSymbolAddress((void**)&xh,    g_xh);
    cudaGetSymbolAddress((void**)&kvh,   g_kvh);
    cudaGetSymbolAddress((void**)&wh,    g_wh);
    cudaGetSymbolAddress((void**)&wtoth, g_wtoth);
    cudaGetSymbolAddress((void**)&weff,  g_weff);

    cudaFuncSetAttribute(k_hgemm_async,
                         cudaFuncAttributeMaxDynamicSharedMemorySize, SMEM_G);

    // 0) zero accumulators + fp16 pre-convert
    k_zero<<<132, 256>>>();
    k_cvt<<<2048, 256>>>(x, w_qkv + 128 * CIN);

    // 1) kv = W_kv @ x  (fp16 pipelined GEMM, fp16 out)
    k_hgemm_async<<<dim3(NPIX / 128, 2, BATCH), 256, SMEM_G>>>(
        wh, 0,
        xh, (long)CIN * NPIX,
        kvh, (long)256 * NPIX,
        nullptr, 1);

    // 2) context partials
    k_context<<<dim3(NPIX / 512, HEADS, BATCH), 256>>>();

    // 3a) fold w_out with normalized context -> W_eff (fp32)
    k_weff<<<dim3(BATCH, 32), 256>>>(w_out);

    // 3b) W_total[b] = W_eff[b] @ W_q  -> fp16 wtot
    k_sgemm_tc<<<dim3(2, 2, BATCH), 256>>>(
        weff, (long)256 * HID,
        w_qkv, 0,
        wtoth, (long)256 * 256,
        256, HID, 256);

    // 4) y[b] = W_total[b] @ x[b] + b_out  (fp16 pipelined GEMM, fp32 out)
    k_hgemm_async<<<dim3(NPIX / 128, 2, BATCH), 256, SMEM_G>>>(
        wtoth, (long)256 * 256,
        xh, (long)CIN * NPIX,
        out, (long)256 * NPIX,
        b_out, 0);
}

// round 7
// speedup vs baseline: 4.1364x; 1.1682x over previous
#include <cuda_runtime.h>
#include <cuda_fp16.h>
#include <math.h>
#include <stdint.h>

#define BATCH 8
#define CIN   256
#define NPIX  16384
#define HEADS 4
#define DH    32
#define HID   128

// ---------------- scratch (device globals; no allocation allowed) ------------
__device__ __half g_xh[(long)BATCH * CIN * NPIX];     // x in fp16
__device__ __half g_kvh[(long)BATCH * 256 * NPIX];    // k rows 0..127, v rows 128..255 (fp16)
__device__ __half g_wh[256 * 256];                    // W_kv in fp16
__device__ __half g_wtoth[BATCH * 256 * 256];         // per-batch effective weight (fp16)
__device__ float  g_ctx[BATCH * HEADS * DH * DH];
__device__ float  g_z[BATCH * HEADS * DH];
__device__ float  g_weff[BATCH * 256 * HID];

__device__ __forceinline__ uint32_t cvt_tf32(float x) {
    uint32_t u;
    asm("cvt.rna.tf32.f32 %0, %1;" : "=r"(u) : "f"(x));
    return u;
}
__device__ __forceinline__ uint32_t smem_u32(const void* p) {
    uint32_t a;
    asm("{ .reg .u64 t; cvta.to.shared.u64 t, %1; cvt.u32.u64 %0, t; }" : "=r"(a) : "l"(p));
    return a;
}
#define CP16(dst, src) \
    asm volatile("cp.async.cg.shared.global [%0], [%1], 16;" :: "r"(dst), "l"(src) : "memory")

// ---------------- zero accumulators ------------------------------------------
__global__ void k_zero() {
    int i = blockIdx.x * blockDim.x + threadIdx.x;
    if (i < BATCH * HEADS * DH * DH) g_ctx[i] = 0.f;
    if (i < BATCH * HEADS * DH)      g_z[i]   = 0.f;
}

// ---------------- fp32 -> fp16 pre-convert (x and W_kv) ----------------------
__global__ void k_cvt(const float* __restrict__ x, const float* __restrict__ wkv) {
    long i = (long)blockIdx.x * blockDim.x + threadIdx.x;
    if (i < 16384) {
        float4 v = ((const float4*)wkv)[i];
        __half2 h0 = __floats2half2_rn(v.x, v.y);
        __half2 h1 = __floats2half2_rn(v.z, v.w);
        uint2 u = { *(uint32_t*)&h0, *(uint32_t*)&h1 };
        ((uint2*)g_wh)[i] = u;
    }
    long stride = (long)gridDim.x * blockDim.x;
    for (long f = i; f < (long)BATCH * CIN * NPIX / 4; f += stride) {
        float4 v = ((const float4*)x)[f];
        __half2 h0 = __floats2half2_rn(v.x, v.y);
        __half2 h1 = __floats2half2_rn(v.z, v.w);
        uint2 u = { *(uint32_t*)&h0, *(uint32_t*)&h1 };
        ((uint2*)g_xh)[f] = u;
    }
}

// =============================================================================
// fp16 cp.async-pipelined GEMM (unchanged from round 5, passing)
// =============================================================================
#define A_BUF 18432   // 128*144
#define B_BUF 17408   // 64*272
#define SMEM_G (2 * A_BUF + 2 * B_BUF)

__device__ __forceinline__ void g2s_tile(uint32_t sb, int buf,
                                         const __half* Arow, const __half* Xb,
                                         long n0, int k0) {
    int tid = threadIdx.x;
    uint32_t abase = sb + buf * A_BUF;
    uint32_t bbase = sb + 2 * A_BUF + buf * B_BUF;
#pragma unroll
    for (int i = 0; i < 4; i++) {
        int f = i * 256 + tid;
        int r = f >> 3, c = f & 7;
        CP16(abase + r * 144 + c * 16, Arow + (long)r * 256 + k0 + c * 8);
    }
#pragma unroll
    for (int i = 0; i < 4; i++) {
        int f = i * 256 + tid;
        int r = f >> 4, c = f & 15;
        CP16(bbase + r * 272 + c * 16, Xb + (long)(k0 + r) * NPIX + n0 + c * 8);
    }
    asm volatile("cp.async.commit_group;" ::: "memory");
}

__global__ __launch_bounds__(256, 2)
void k_hgemm_async(const __half* __restrict__ A, long sA,
                   const __half* __restrict__ X, long sX,
                   void* __restrict__ Cv, long sC,
                   const float* __restrict__ bias, int half_out)
{
    extern __shared__ char smem[];
    uint32_t sb = smem_u32(smem);

    int b = blockIdx.z;
    const __half* Ab = A + (long)b * sA + (long)blockIdx.y * 128 * 256;
    const __half* Xb = X + (long)b * sX;
    long n0 = (long)blockIdx.x * 128;
    int m0 = blockIdx.y * 128;

    int tid  = threadIdx.x;
    int wid  = tid >> 5, lane = tid & 31;
    int g4   = lane >> 2, q = lane & 3;
    int wm   = (wid >> 2) * 64;
    int wn   = (wid & 3) * 32;
    int rowoff = (lane & 7) + ((lane >> 3) & 1) * 8;
    int colsel = (lane >> 4) * 8;

    float acc[4][4][4];
#pragma unroll
    for (int i = 0; i < 4; i++)
#pragma unroll
        for (int j = 0; j < 4; j++)
#pragma unroll
            for (int r = 0; r < 4; r++) acc[i][j][r] = 0.f;

    g2s_tile(sb, 0, Ab, Xb, n0, 0);

#pragma unroll 1
    for (int t = 0; t < 4; t++) {
        if (t < 3) g2s_tile(sb, (t + 1) & 1, Ab, Xb, n0, (t + 1) * 64);
        if (t < 3) { asm volatile("cp.async.wait_group 1;" ::: "memory"); }
        else       { asm volatile("cp.async.wait_group 0;" ::: "memory"); }
        __syncthreads();

        uint32_t abase = sb + (t & 1) * A_BUF;
        uint32_t bbase = sb + 2 * A_BUF + (t & 1) * B_BUF;
#pragma unroll
        for (int ks = 0; ks < 64; ks += 16) {
            uint32_t af[4][4];
#pragma unroll
            for (int mf = 0; mf < 4; mf++) {
                uint32_t addr = abase + (uint32_t)((wm + mf * 16 + rowoff) * 144
                                                   + (ks + colsel) * 2);
                asm volatile(
                    "ldmatrix.sync.aligned.m8n8.x4.shared.b16 {%0,%1,%2,%3}, [%4];"
                    : "=r"(af[mf][0]), "=r"(af[mf][1]), "=r"(af[mf][2]), "=r"(af[mf][3])
                    : "r"(addr));
            }
            uint32_t bf[2][4];
#pragma unroll
            for (int np = 0; np < 2; np++) {
                uint32_t addr = bbase + (uint32_t)((ks + rowoff) * 272
                                                   + (wn + np * 16 + colsel) * 2);
                asm volatile(
                    "ldmatrix.sync.aligned.m8n8.x4.trans.shared.b16 {%0,%1,%2,%3}, [%4];"
                    : "=r"(bf[np][0]), "=r"(bf[np][1]), "=r"(bf[np][2]), "=r"(bf[np][3])
                    : "r"(addr));
            }
#pragma unroll
            for (int nf = 0; nf < 4; nf++) {
                uint32_t b0 = bf[nf >> 1][(nf & 1) * 2];
                uint32_t b1 = bf[nf >> 1][(nf & 1) * 2 + 1];
#pragma unroll
                for (int mf = 0; mf < 4; mf++) {
                    asm volatile(
                        "mma.sync.aligned.m16n8k16.row.col.f32.f16.f16.f32 "
                        "{%0,%1,%2,%3},{%4,%5,%6,%7},{%8,%9},{%0,%1,%2,%3};"
                        : "+f"(acc[mf][nf][0]), "+f"(acc[mf][nf][1]),
                          "+f"(acc[mf][nf][2]), "+f"(acc[mf][nf][3])
                        : "r"(af[mf][0]), "r"(af[mf][1]),
                          "r"(af[mf][2]), "r"(af[mf][3]),
                          "r"(b0), "r"(b1));
                }
            }
        }
        __syncthreads();
    }

    if (half_out) {
        __half* Ch = (__half*)Cv + (long)b * sC;
#pragma unroll
        for (int mf = 0; mf < 4; mf++) {
            long mrow = m0 + wm + mf * 16 + g4;
#pragma unroll
            for (int nf = 0; nf < 4; nf++) {
                long nc = n0 + wn + nf * 8 + 2 * q;
                *(__half2*)&Ch[mrow * NPIX + nc] =
                    __floats2half2_rn(acc[mf][nf][0], acc[mf][nf][1]);
                *(__half2*)&Ch[(mrow + 8) * NPIX + nc] =
                    __floats2half2_rn(acc[mf][nf][2], acc[mf][nf][3]);
            }
        }
    } else {
        float* Cf = (float*)Cv + (long)b * sC;
#pragma unroll
        for (int mf = 0; mf < 4; mf++) {
            long mrow = m0 + wm + mf * 16 + g4;
            float bv0 = bias ? bias[mrow]     : 0.f;
            float bv1 = bias ? bias[mrow + 8] : 0.f;
#pragma unroll
            for (int nf = 0; nf < 4; nf++) {
                long nc = n0 + wn + nf * 8 + 2 * q;
                float2 v0 = { acc[mf][nf][0] + bv0, acc[mf][nf][1] + bv0 };
                float2 v1 = { acc[mf][nf][2] + bv1, acc[mf][nf][3] + bv1 };
                *(float2*)&Cf[mrow * NPIX + nc]       = v0;
                *(float2*)&Cf[(mrow + 8) * NPIX + nc] = v1;
            }
        }
    }
}

// =============================================================================
// Tensor-core context: ctx[d,e] = sum_n exp(k[d,n]) * v[e,n]  per (b,h)
// A = exp(k) fp16 [d][n], B = v fp16 [e][n]. Fragments fed by DIRECT 4-byte
// LDS at the documented m16n8k16 per-lane offsets (all even-half -> aligned,
// bank = (4*row + lane%4) mod 32 -> conflict-free).
// Grid (16, HEADS, BATCH), 128 thr. Warp-private 32x136-half tiles.
// =============================================================================
#define CTX_ESZ 8704           // 32 rows * 136 halves * 2B
#define CTX_SMEM (8 * CTX_ESZ) // 69632

__global__ __launch_bounds__(128)
void k_context_mma()
{
    extern __shared__ char smem[];
    int tid = threadIdx.x, wid = tid >> 5, lane = tid & 31;
    int b = blockIdx.z, h = blockIdx.y;
    int g4 = lane >> 2, q = lane & 3;

    __half* Ew = (__half*)(smem + wid * CTX_ESZ);
    __half* Vw = (__half*)(smem + 4 * CTX_ESZ + wid * CTX_ESZ);

    const __half* kb = g_kvh + (long)(b * 256 + h * 32) * NPIX;
    const __half* vb = kb + (long)128 * NPIX;
    float* zp = g_z + (b * HEADS + h) * DH;

    float acc[2][4][4];
#pragma unroll
    for (int i = 0; i < 2; i++)
#pragma unroll
        for (int j = 0; j < 4; j++)
#pragma unroll
            for (int r = 0; r < 4; r++) acc[i][j][r] = 0.f;
    float zacc = 0.f;   // this lane accumulates z for row == lane

#pragma unroll 1
    for (int it = 0; it < 2; it++) {
        long n0 = (long)blockIdx.x * 1024 + it * 512 + wid * 128;

        // ---- load: exp(k) -> fp16 Ew; v -> Vw; z via warp shuffles
#pragma unroll 4
        for (int r = 0; r < 32; r++) {
            uint2 ku = *(const uint2*)&kb[(long)r * NPIX + n0 + lane * 4];
            __half2 k01 = *(__half2*)&ku.x, k23 = *(__half2*)&ku.y;
            float2 f01 = __half22float2(k01), f23 = __half22float2(k23);
            float e0 = expf(f01.x), e1 = expf(f01.y);
            float e2 = expf(f23.x), e3 = expf(f23.y);
            __half2 h0 = __floats2half2_rn(e0, e1), h1 = __floats2half2_rn(e2, e3);
            uint2 eu = { *(uint32_t*)&h0, *(uint32_t*)&h1 };
            *(uint2*)&Ew[r * 136 + lane * 4] = eu;
            uint2 vu = *(const uint2*)&vb[(long)r * NPIX + n0 + lane * 4];
            *(uint2*)&Vw[r * 136 + lane * 4] = vu;
            float s = (e0 + e1) + (e2 + e3);
            s += __shfl_xor_sync(0xFFFFFFFFu, s, 16);
            s += __shfl_xor_sync(0xFFFFFFFFu, s, 8);
            s += __shfl_xor_sync(0xFFFFFFFFu, s, 4);
            s += __shfl_xor_sync(0xFFFFFFFFu, s, 2);
            s += __shfl_xor_sync(0xFFFFFFFFu, s, 1);
            if (lane == r) zacc += s;
        }
        __syncwarp();

        // ---- mma: 8 k16 steps; direct LDS fragment feeds
#pragma unroll
        for (int ks = 0; ks < 128; ks += 16) {
            int fc = ks + 2 * q;      // fragment k column (even)
#pragma unroll
            for (int mf = 0; mf < 2; mf++) {
                int d0 = mf * 16 + g4;
                uint32_t a0 = *(const uint32_t*)&Ew[d0 * 136 + fc];
                uint32_t a1 = *(const uint32_t*)&Ew[(d0 + 8) * 136 + fc];
                uint32_t a2 = *(const uint32_t*)&Ew[d0 * 136 + fc + 8];
                uint32_t a3 = *(const uint32_t*)&Ew[(d0 + 8) * 136 + fc + 8];
#pragma unroll
                for (int nf = 0; nf < 4; nf++) {
                    int e0r = nf * 8 + g4;
                    uint32_t b0 = *(const uint32_t*)&Vw[e0r * 136 + fc];
                    uint32_t b1 = *(const uint32_t*)&Vw[e0r * 136 + fc + 8];
                    asm volatile(
                        "mma.sync.aligned.m16n8k16.row.col.f32.f16.f16.f32 "
                        "{%0,%1,%2,%3},{%4,%5,%6,%7},{%8,%9},{%0,%1,%2,%3};"
                        : "+f"(acc[mf][nf][0]), "+f"(acc[mf][nf][1]),
                          "+f"(acc[mf][nf][2]), "+f"(acc[mf][nf][3])
                        : "r"(a0), "r"(a1), "r"(a2), "r"(a3),
                          "r"(b0), "r"(b1));
                }
            }
        }
        __syncwarp();
    }

    atomicAdd(&zp[lane], zacc);

    // ---- block reduce: each warp writes its 32x32 tile into its E area
    float* red = (float*)(smem + wid * CTX_ESZ);
#pragma unroll
    for (int mf = 0; mf < 2; mf++)
#pragma unroll
        for (int nf = 0; nf < 4; nf++) {
            int dd = mf * 16 + g4, ee = nf * 8 + 2 * q;
            red[dd * 32 + ee]           = acc[mf][nf][0];
            red[dd * 32 + ee + 1]       = acc[mf][nf][1];
            red[(dd + 8) * 32 + ee]     = acc[mf][nf][2];
            red[(dd + 8) * 32 + ee + 1] = acc[mf][nf][3];
        }
    __syncthreads();

    float* cp = g_ctx + (long)(b * HEADS + h) * 1024;
    const float* r0 = (const float*)(smem);
    const float* r1 = (const float*)(smem + CTX_ESZ);
    const float* r2 = (const float*)(smem + 2 * CTX_ESZ);
    const float* r3 = (const float*)(smem + 3 * CTX_ESZ);
#pragma unroll
    for (int j = tid; j < 1024; j += 128) {
        float s = (r0[j] + r1[j]) + (r2[j] + r3[j]);
        atomicAdd(&cp[j], s);
    }
}

// ---------------- tf32 mma SGEMM -> fp16 out (tiny fold GEMM) ----------------
__global__ __launch_bounds__(256, 2)
void k_sgemm_tc(const float* __restrict__ A, long sA,
                const float* __restrict__ X, long sX,
                __half* __restrict__ C, long sC,
                int M, int K, int N)
{
    const int BM = 128, BN = 128, BK = 32;
    __shared__ uint32_t As[BK][BM + 4];
    __shared__ uint32_t Bs[BK][BN + 4];

    int b = blockIdx.z;
    const float* Ab = A + (long)b * sA;
    const float* Xb = X + (long)b * sX;
    __half*      Cb = C + (long)b * sC;
    int m0 = blockIdx.y * BM, n0 = blockIdx.x * BN;
    int tid  = threadIdx.x;
    int wid  = tid >> 5, lane = tid & 31;
    int g4   = lane >> 2, q = lane & 3;
    int wm   = (wid >> 2) * 64;
    int wn   = (wid & 3) * 32;

    float acc[4][4][4];
#pragma unroll
    for (int i = 0; i < 4; i++)
#pragma unroll
        for (int j = 0; j < 4; j++)
#pragma unroll
            for (int r = 0; r < 4; r++) acc[i][j][r] = 0.f;

    for (int k0 = 0; k0 < K; k0 += BK) {
#pragma unroll
        for (int i = 0; i < 4; i++) {
            int f  = i * 256 + tid;
            int m  = f >> 3, k4 = (f & 7) << 2;
            float4 v = *(const float4*)&Ab[(long)(m0 + m) * K + k0 + k4];
            As[k4 + 0][m] = cvt_tf32(v.x); As[k4 + 1][m] = cvt_tf32(v.y);
            As[k4 + 2][m] = cvt_tf32(v.z); As[k4 + 3][m] = cvt_tf32(v.w);
        }
#pragma unroll
        for (int i = 0; i < 4; i++) {
            int f  = i * 256 + tid;
            int kk = f >> 5, n4 = (f & 31) << 2;
            float4 v = *(const float4*)&Xb[(long)(k0 + kk) * N + n0 + n4];
            uint4 u;
            u.x = cvt_tf32(v.x); u.y = cvt_tf32(v.y);
            u.z = cvt_tf32(v.z); u.w = cvt_tf32(v.w);
            *(uint4*)&Bs[kk][n4] = u;
        }
        __syncthreads();

#pragma unroll
        for (int ks = 0; ks < BK; ks += 8) {
            uint32_t af[4][4];
#pragma unroll
            for (int mf = 0; mf < 4; mf++) {
                int mb = wm + mf * 16;
                af[mf][0] = As[ks + q    ][mb + g4    ];
                af[mf][1] = As[ks + q    ][mb + g4 + 8];
                af[mf][2] = As[ks + q + 4][mb + g4    ];
                af[mf][3] = As[ks + q + 4][mb + g4 + 8];
            }
#pragma unroll
            for (int nf = 0; nf < 4; nf++) {
                int nb = wn + nf * 8;
                uint32_t b0 = Bs[ks + q    ][nb + g4];
                uint32_t b1 = Bs[ks + q + 4][nb + g4];
#pragma unroll
                for (int mf = 0; mf < 4; mf++) {
                    asm volatile(
                        "mma.sync.aligned.m16n8k8.row.col.f32.tf32.tf32.f32 "
                        "{%0,%1,%2,%3},{%4,%5,%6,%7},{%8,%9},{%0,%1,%2,%3};"
                        : "+f"(acc[mf][nf][0]), "+f"(acc[mf][nf][1]),
                          "+f"(acc[mf][nf][2]), "+f"(acc[mf][nf][3])
                        : "r"(af[mf][0]), "r"(af[mf][1]),
                          "r"(af[mf][2]), "r"(af[mf][3]),
                          "r"(b0), "r"(b1));
                }
            }
        }
        __syncthreads();
    }

#pragma unroll
    for (int mf = 0; mf < 4; mf++) {
        int mrow = m0 + wm + mf * 16 + g4;
#pragma unroll
        for (int nf = 0; nf < 4; nf++) {
            int nc = n0 + wn + nf * 8 + 2 * q;
            *(__half2*)&Cb[(long)mrow * N + nc] =
                __floats2half2_rn(acc[mf][nf][0], acc[mf][nf][1]);
            *(__half2*)&Cb[(long)(mrow + 8) * N + nc] =
                __floats2half2_rn(acc[mf][nf][2], acc[mf][nf][3]);
        }
    }
}

// ---------------- fold: W_eff[b][o][h*32+d] = sum_e w_out[o][h*32+e]*ctxn[h][d][e]
__global__ __launch_bounds__(256)
void k_weff(const float* __restrict__ w_out)
{
    __shared__ float ctxn[HEADS][DH][DH + 1];
    __shared__ float zinv[HEADS * DH];
    int b = blockIdx.x, oc = blockIdx.y;
    int tid = threadIdx.x;
    if (tid < 128) zinv[tid] = 1.0f / g_z[b * 128 + tid];
    __syncthreads();
    for (int i = tid; i < 4096; i += 256) {
        int h = i >> 10, d = (i >> 5) & 31, e = i & 31;
        ctxn[h][d][e] = g_ctx[b * 4096 + i] * zinv[h * 32 + d];
    }
    __syncthreads();
    for (int i = tid; i < 8 * 128; i += 256) {
        int ol = i >> 7;
        int hd = i & 127;
        int h = hd >> 5, d = hd & 31;
        int o = oc * 8 + ol;
        const float* wrow = w_out + o * HID + h * 32;
        float s = 0.f;
#pragma unroll
        for (int e = 0; e < 32; e++) s = fmaf(wrow[e], ctxn[h][d][e], s);
        g_weff[((long)b * 256 + o) * HID + hd] = s;
    }
}

// ---------------- launch --------------------------------------------------
extern "C" void kernel_launch(void* const* d_in, const int* in_sizes, int n_in,
                              void* d_out, int out_size)
{
    const float *x = nullptr, *w_qkv = nullptr, *w_out = nullptr, *b_out = nullptr;
    for (int i = 0; i < n_in; i++) {
        const float* p = (const float*)d_in[i];
        if      (in_sizes[i] == BATCH * CIN * NPIX) x     = p;
        else if (in_sizes[i] == 3 * HID * CIN)      w_qkv = p;
        else if (in_sizes[i] == CIN * HID)          w_out = p;
        else if (in_sizes[i] == CIN)                b_out = p;
    }
    float* out = (float*)d_out;

    __half *xh, *kvh, *wh, *wtoth;
    float *weff;
    cudaGetSymbolAddress((void**)&xh,    g_xh);
    cudaGetSymbolAddress((void**)&kvh,   g_kvh);
    cudaGetSymbolAddress((void**)&wh,    g_wh);
    cudaGetSymbolAddress((void**)&wtoth, g_wtoth);
    cudaGetSymbolAddress((void**)&weff,  g_weff);

    cudaFuncSetAttribute(k_hgemm_async,
                         cudaFuncAttributeMaxDynamicSharedMemorySize, SMEM_G);
    cudaFuncSetAttribute(k_context_mma,
                         cudaFuncAttributeMaxDynamicSharedMemorySize, CTX_SMEM);

    // 0) zero accumulators + fp16 pre-convert
    k_zero<<<132, 256>>>();
    k_cvt<<<2048, 256>>>(x, w_qkv + 128 * CIN);

    // 1) kv = W_kv @ x  (fp16 pipelined GEMM, fp16 out)
    k_hgemm_async<<<dim3(NPIX / 128, 2, BATCH), 256, SMEM_G>>>(
        wh, 0,
        xh, (long)CIN * NPIX,
        kvh, (long)256 * NPIX,
        nullptr, 1);

    // 2) context via tensor cores (direct-LDS fragment feeds)
    k_context_mma<<<dim3(16, HEADS, BATCH), 128, CTX_SMEM>>>();

    // 3a) fold w_out with normalized context -> W_eff (fp32)
    k_weff<<<dim3(BATCH, 32), 256>>>(w_out);

    // 3b) W_total[b] = W_eff[b] @ W_q  -> fp16 wtot
    k_sgemm_tc<<<dim3(2, 2, BATCH), 256>>>(
        weff, (long)256 * HID,
        w_qkv, 0,
        wtoth, (long)256 * 256,
        256, HID, 256);

    // 4) y[b] = W_total[b] @ x[b] + b_out  (fp16 pipelined GEMM, fp32 out)
    k_hgemm_async<<<dim3(NPIX / 128, 2, BATCH), 256, SMEM_G>>>(
        wtoth, (long)256 * 256,
        xh, (long)CIN * NPIX,
        out, (long)256 * NPIX,
        b_out, 0);
}

// round 8
// speedup vs baseline: 4.8829x; 1.1805x over previous
#include <cuda_runtime.h>
#include <cuda_fp16.h>
#include <math.h>
#include <stdint.h>

#define BATCH 8
#define CIN   256
#define NPIX  16384
#define HEADS 4
#define DH    32
#define HID   128

// ---------------- scratch (device globals; no allocation allowed) ------------
__device__ __half g_xh[(long)BATCH * CIN * NPIX];     // x in fp16
__device__ __half g_kvh[(long)BATCH * 256 * NPIX];    // k rows 0..127, v rows 128..255 (fp16)
__device__ __half g_wh[256 * 256];                    // W_kv in fp16
__device__ __half g_wtoth[BATCH * 256 * 256];         // per-batch effective weight (fp16)
__device__ float  g_ctx[BATCH * HEADS * DH * DH];
__device__ float  g_z[BATCH * HEADS * DH];
__device__ float  g_weff[BATCH * 256 * HID];

__device__ __forceinline__ uint32_t cvt_tf32(float x) {
    uint32_t u;
    asm("cvt.rna.tf32.f32 %0, %1;" : "=r"(u) : "f"(x));
    return u;
}
__device__ __forceinline__ uint32_t smem_u32(const void* p) {
    uint32_t a;
    asm("{ .reg .u64 t; cvta.to.shared.u64 t, %1; cvt.u32.u64 %0, t; }" : "=r"(a) : "l"(p));
    return a;
}
#define CP16(dst, src) \
    asm volatile("cp.async.cg.shared.global [%0], [%1], 16;" :: "r"(dst), "l"(src) : "memory")

// ---------------- zero accumulators ------------------------------------------
__global__ void k_zero() {
    int i = blockIdx.x * blockDim.x + threadIdx.x;
    if (i < BATCH * HEADS * DH * DH) g_ctx[i] = 0.f;
    if (i < BATCH * HEADS * DH)      g_z[i]   = 0.f;
}

// ---------------- fp32 -> fp16 pre-convert (x and W_kv) ----------------------
__global__ void k_cvt(const float* __restrict__ x, const float* __restrict__ wkv) {
    long i = (long)blockIdx.x * blockDim.x + threadIdx.x;
    if (i < 16384) {
        float4 v = ((const float4*)wkv)[i];
        __half2 h0 = __floats2half2_rn(v.x, v.y);
        __half2 h1 = __floats2half2_rn(v.z, v.w);
        uint2 u = { *(uint32_t*)&h0, *(uint32_t*)&h1 };
        ((uint2*)g_wh)[i] = u;
    }
    long stride = (long)gridDim.x * blockDim.x;
    for (long f = i; f < (long)BATCH * CIN * NPIX / 4; f += stride) {
        float4 v = ((const float4*)x)[f];
        __half2 h0 = __floats2half2_rn(v.x, v.y);
        __half2 h1 = __floats2half2_rn(v.z, v.w);
        uint2 u = { *(uint32_t*)&h0, *(uint32_t*)&h1 };
        ((uint2*)g_xh)[f] = u;
    }
}

// =============================================================================
// fp16 cp.async-pipelined GEMM (unchanged, passing)
// =============================================================================
#define A_BUF 18432   // 128*144
#define B_BUF 17408   // 64*272
#define SMEM_G (2 * A_BUF + 2 * B_BUF)

__device__ __forceinline__ void g2s_tile(uint32_t sb, int buf,
                                         const __half* Arow, const __half* Xb,
                                         long n0, int k0) {
    int tid = threadIdx.x;
    uint32_t abase = sb + buf * A_BUF;
    uint32_t bbase = sb + 2 * A_BUF + buf * B_BUF;
#pragma unroll
    for (int i = 0; i < 4; i++) {
        int f = i * 256 + tid;
        int r = f >> 3, c = f & 7;
        CP16(abase + r * 144 + c * 16, Arow + (long)r * 256 + k0 + c * 8);
    }
#pragma unroll
    for (int i = 0; i < 4; i++) {
        int f = i * 256 + tid;
        int r = f >> 4, c = f & 15;
        CP16(bbase + r * 272 + c * 16, Xb + (long)(k0 + r) * NPIX + n0 + c * 8);
    }
    asm volatile("cp.async.commit_group;" ::: "memory");
}

__global__ __launch_bounds__(256, 2)
void k_hgemm_async(const __half* __restrict__ A, long sA,
                   const __half* __restrict__ X, long sX,
                   void* __restrict__ Cv, long sC,
                   const float* __restrict__ bias, int half_out)
{
    extern __shared__ char smem[];
    uint32_t sb = smem_u32(smem);

    int b = blockIdx.z;
    const __half* Ab = A + (long)b * sA + (long)blockIdx.y * 128 * 256;
    const __half* Xb = X + (long)b * sX;
    long n0 = (long)blockIdx.x * 128;
    int m0 = blockIdx.y * 128;

    int tid  = threadIdx.x;
    int wid  = tid >> 5, lane = tid & 31;
    int g4   = lane >> 2, q = lane & 3;
    int wm   = (wid >> 2) * 64;
    int wn   = (wid & 3) * 32;
    int rowoff = (lane & 7) + ((lane >> 3) & 1) * 8;
    int colsel = (lane >> 4) * 8;

    float acc[4][4][4];
#pragma unroll
    for (int i = 0; i < 4; i++)
#pragma unroll
        for (int j = 0; j < 4; j++)
#pragma unroll
            for (int r = 0; r < 4; r++) acc[i][j][r] = 0.f;

    g2s_tile(sb, 0, Ab, Xb, n0, 0);

#pragma unroll 1
    for (int t = 0; t < 4; t++) {
        if (t < 3) g2s_tile(sb, (t + 1) & 1, Ab, Xb, n0, (t + 1) * 64);
        if (t < 3) { asm volatile("cp.async.wait_group 1;" ::: "memory"); }
        else       { asm volatile("cp.async.wait_group 0;" ::: "memory"); }
        __syncthreads();

        uint32_t abase = sb + (t & 1) * A_BUF;
        uint32_t bbase = sb + 2 * A_BUF + (t & 1) * B_BUF;
#pragma unroll
        for (int ks = 0; ks < 64; ks += 16) {
            uint32_t af[4][4];
#pragma unroll
            for (int mf = 0; mf < 4; mf++) {
                uint32_t addr = abase + (uint32_t)((wm + mf * 16 + rowoff) * 144
                                                   + (ks + colsel) * 2);
                asm volatile(
                    "ldmatrix.sync.aligned.m8n8.x4.shared.b16 {%0,%1,%2,%3}, [%4];"
                    : "=r"(af[mf][0]), "=r"(af[mf][1]), "=r"(af[mf][2]), "=r"(af[mf][3])
                    : "r"(addr));
            }
            uint32_t bf[2][4];
#pragma unroll
            for (int np = 0; np < 2; np++) {
                uint32_t addr = bbase + (uint32_t)((ks + rowoff) * 272
                                                   + (wn + np * 16 + colsel) * 2);
                asm volatile(
                    "ldmatrix.sync.aligned.m8n8.x4.trans.shared.b16 {%0,%1,%2,%3}, [%4];"
                    : "=r"(bf[np][0]), "=r"(bf[np][1]), "=r"(bf[np][2]), "=r"(bf[np][3])
                    : "r"(addr));
            }
#pragma unroll
            for (int nf = 0; nf < 4; nf++) {
                uint32_t b0 = bf[nf >> 1][(nf & 1) * 2];
                uint32_t b1 = bf[nf >> 1][(nf & 1) * 2 + 1];
#pragma unroll
                for (int mf = 0; mf < 4; mf++) {
                    asm volatile(
                        "mma.sync.aligned.m16n8k16.row.col.f32.f16.f16.f32 "
                        "{%0,%1,%2,%3},{%4,%5,%6,%7},{%8,%9},{%0,%1,%2,%3};"
                        : "+f"(acc[mf][nf][0]), "+f"(acc[mf][nf][1]),
                          "+f"(acc[mf][nf][2]), "+f"(acc[mf][nf][3])
                        : "r"(af[mf][0]), "r"(af[mf][1]),
                          "r"(af[mf][2]), "r"(af[mf][3]),
                          "r"(b0), "r"(b1));
                }
            }
        }
        __syncthreads();
    }

    if (half_out) {
        __half* Ch = (__half*)Cv + (long)b * sC;
#pragma unroll
        for (int mf = 0; mf < 4; mf++) {
            long mrow = m0 + wm + mf * 16 + g4;
#pragma unroll
            for (int nf = 0; nf < 4; nf++) {
                long nc = n0 + wn + nf * 8 + 2 * q;
                *(__half2*)&Ch[mrow * NPIX + nc] =
                    __floats2half2_rn(acc[mf][nf][0], acc[mf][nf][1]);
                *(__half2*)&Ch[(mrow + 8) * NPIX + nc] =
                    __floats2half2_rn(acc[mf][nf][2], acc[mf][nf][3]);
            }
        }
    } else {
        float* Cf = (float*)Cv + (long)b * sC;
#pragma unroll
        for (int mf = 0; mf < 4; mf++) {
            long mrow = m0 + wm + mf * 16 + g4;
            float bv0 = bias ? bias[mrow]     : 0.f;
            float bv1 = bias ? bias[mrow + 8] : 0.f;
#pragma unroll
            for (int nf = 0; nf < 4; nf++) {
                long nc = n0 + wn + nf * 8 + 2 * q;
                float2 v0 = { acc[mf][nf][0] + bv0, acc[mf][nf][1] + bv0 };
                float2 v1 = { acc[mf][nf][2] + bv1, acc[mf][nf][3] + bv1 };
                *(float2*)&Cf[mrow * NPIX + nc]       = v0;
                *(float2*)&Cf[(mrow + 8) * NPIX + nc] = v1;
            }
        }
    }
}

// =============================================================================
// Tensor-core context: ctx[d,e] = sum_n exp(k[d,n]) * v[e,n]  per (b,h).
// z[d] = sum_n exp(k[d,n]) computed by an EXTRA mma with B = fp16 ones
// (register constant) -- no shuffles, no extra loads.
// Grid (32, HEADS, BATCH), 128 thr; each warp owns one 128-px subtile.
// uint4 loads (2 rows/iter), __expf. Direct-LDS fragment feeds (verified).
// =============================================================================
#define CTX_ESZ 8704           // 32 rows * 136 halves * 2B
#define CTX_SMEM (8 * CTX_ESZ) // 69632

__global__ __launch_bounds__(128)
void k_context_mma()
{
    extern __shared__ char smem[];
    int tid = threadIdx.x, wid = tid >> 5, lane = tid & 31;
    int b = blockIdx.z, h = blockIdx.y;
    int g4 = lane >> 2, q = lane & 3;

    __half* Ew = (__half*)(smem + wid * CTX_ESZ);
    __half* Vw = (__half*)(smem + 4 * CTX_ESZ + wid * CTX_ESZ);

    const __half* kb = g_kvh + (long)(b * 256 + h * 32) * NPIX;
    const __half* vb = kb + (long)128 * NPIX;

    long n0 = (long)blockIdx.x * 512 + wid * 128;

    // ---- load: exp(k) -> Ew, v -> Vw. 16B per lane, 2 rows/iter, no deps.
    int lr = lane >> 4;            // 0/1: row parity
    int lc = (lane & 15) * 8;      // column (halves)
#pragma unroll
    for (int i = 0; i < 16; i++) {
        int r = 2 * i + lr;
        long off = (long)r * NPIX + n0 + lc;
        uint4 ku = *(const uint4*)&kb[off];
        uint4 vu = *(const uint4*)&vb[off];
        const __half2* kh = (const __half2*)&ku;
        uint4 eu;
        __half2* eh = (__half2*)&eu;
#pragma unroll
        for (int j = 0; j < 4; j++) {
            float2 f = __half22float2(kh[j]);
            eh[j] = __floats2half2_rn(__expf(f.x), __expf(f.y));
        }
        *(uint4*)&Ew[r * 136 + lc] = eu;
        *(uint4*)&Vw[r * 136 + lc] = vu;
    }
    __syncwarp();

    float acc[2][4][4];
#pragma unroll
    for (int i = 0; i < 2; i++)
#pragma unroll
        for (int j = 0; j < 4; j++)
#pragma unroll
            for (int r = 0; r < 4; r++) acc[i][j][r] = 0.f;
    float zac[2][4];
#pragma unroll
    for (int i = 0; i < 2; i++)
#pragma unroll
        for (int r = 0; r < 4; r++) zac[i][r] = 0.f;

    const uint32_t ONES = 0x3C003C00u;   // half2(1.0, 1.0)

    // ---- mma: 8 k16 steps; direct LDS fragment feeds + z-ones mma
#pragma unroll
    for (int ks = 0; ks < 128; ks += 16) {
        int fc = ks + 2 * q;
#pragma unroll
        for (int mf = 0; mf < 2; mf++) {
            int d0 = mf * 16 + g4;
            uint32_t a0 = *(const uint32_t*)&Ew[d0 * 136 + fc];
            uint32_t a1 = *(const uint32_t*)&Ew[(d0 + 8) * 136 + fc];
            uint32_t a2 = *(const uint32_t*)&Ew[d0 * 136 + fc + 8];
            uint32_t a3 = *(const uint32_t*)&Ew[(d0 + 8) * 136 + fc + 8];
            // z partial: E @ ones
            asm volatile(
                "mma.sync.aligned.m16n8k16.row.col.f32.f16.f16.f32 "
                "{%0,%1,%2,%3},{%4,%5,%6,%7},{%8,%9},{%0,%1,%2,%3};"
                : "+f"(zac[mf][0]), "+f"(zac[mf][1]),
                  "+f"(zac[mf][2]), "+f"(zac[mf][3])
                : "r"(a0), "r"(a1), "r"(a2), "r"(a3),
                  "r"(ONES), "r"(ONES));
#pragma unroll
            for (int nf = 0; nf < 4; nf++) {
                int e0r = nf * 8 + g4;
                uint32_t b0 = *(const uint32_t*)&Vw[e0r * 136 + fc];
                uint32_t b1 = *(const uint32_t*)&Vw[e0r * 136 + fc + 8];
                asm volatile(
                    "mma.sync.aligned.m16n8k16.row.col.f32.f16.f16.f32 "
                    "{%0,%1,%2,%3},{%4,%5,%6,%7},{%8,%9},{%0,%1,%2,%3};"
                    : "+f"(acc[mf][nf][0]), "+f"(acc[mf][nf][1]),
                      "+f"(acc[mf][nf][2]), "+f"(acc[mf][nf][3])
                    : "r"(a0), "r"(a1), "r"(a2), "r"(a3),
                      "r"(b0), "r"(b1));
            }
        }
    }
    __syncwarp();

    // ---- z atomics: lanes q==0 hold column 0 of the ones-mma result
    if (q == 0) {
        float* zp = g_z + (b * HEADS + h) * DH;
        atomicAdd(&zp[g4],      zac[0][0]);
        atomicAdd(&zp[g4 + 8],  zac[0][2]);
        atomicAdd(&zp[g4 + 16], zac[1][0]);
        atomicAdd(&zp[g4 + 24], zac[1][2]);
    }

    // ---- block reduce: each warp writes its 32x32 tile into its E area
    float* red = (float*)(smem + wid * CTX_ESZ);
#pragma unroll
    for (int mf = 0; mf < 2; mf++)
#pragma unroll
        for (int nf = 0; nf < 4; nf++) {
            int dd = mf * 16 + g4, ee = nf * 8 + 2 * q;
            red[dd * 32 + ee]           = acc[mf][nf][0];
            red[dd * 32 + ee + 1]       = acc[mf][nf][1];
            red[(dd + 8) * 32 + ee]     = acc[mf][nf][2];
            red[(dd + 8) * 32 + ee + 1] = acc[mf][nf][3];
        }
    __syncthreads();

    float* cp = g_ctx + (long)(b * HEADS + h) * 1024;
    const float* r0 = (const float*)(smem);
    const float* r1 = (const float*)(smem + CTX_ESZ);
    const float* r2 = (const float*)(smem + 2 * CTX_ESZ);
    const float* r3 = (const float*)(smem + 3 * CTX_ESZ);
#pragma unroll
    for (int j = tid; j < 1024; j += 128) {
        float s = (r0[j] + r1[j]) + (r2[j] + r3[j]);
        atomicAdd(&cp[j], s);
    }
}

// ---------------- tf32 mma SGEMM -> fp16 out (tiny fold GEMM) ----------------
__global__ __launch_bounds__(256, 2)
void k_sgemm_tc(const float* __restrict__ A, long sA,
                const float* __restrict__ X, long sX,
                __half* __restrict__ C, long sC,
                int M, int K, int N)
{
    const int BM = 128, BN = 128, BK = 32;
    __shared__ uint32_t As[BK][BM + 4];
    __shared__ uint32_t Bs[BK][BN + 4];

    int b = blockIdx.z;
    const float* Ab = A + (long)b * sA;
    const float* Xb = X + (long)b * sX;
    __half*      Cb = C + (long)b * sC;
    int m0 = blockIdx.y * BM, n0 = blockIdx.x * BN;
    int tid  = threadIdx.x;
    int wid  = tid >> 5, lane = tid & 31;
    int g4   = lane >> 2, q = lane & 3;
    int wm   = (wid >> 2) * 64;
    int wn   = (wid & 3) * 32;

    float acc[4][4][4];
#pragma unroll
    for (int i = 0; i < 4; i++)
#pragma unroll
        for (int j = 0; j < 4; j++)
#pragma unroll
            for (int r = 0; r < 4; r++) acc[i][j][r] = 0.f;

    for (int k0 = 0; k0 < K; k0 += BK) {
#pragma unroll
        for (int i = 0; i < 4; i++) {
            int f  = i * 256 + tid;
            int m  = f >> 3, k4 = (f & 7) << 2;
            float4 v = *(const float4*)&Ab[(long)(m0 + m) * K + k0 + k4];
            As[k4 + 0][m] = cvt_tf32(v.x); As[k4 + 1][m] = cvt_tf32(v.y);
            As[k4 + 2][m] = cvt_tf32(v.z); As[k4 + 3][m] = cvt_tf32(v.w);
        }
#pragma unroll
        for (int i = 0; i < 4; i++) {
            int f  = i * 256 + tid;
            int kk = f >> 5, n4 = (f & 31) << 2;
            float4 v = *(const float4*)&Xb[(long)(k0 + kk) * N + n0 + n4];
            uint4 u;
            u.x = cvt_tf32(v.x); u.y = cvt_tf32(v.y);
            u.z = cvt_tf32(v.z); u.w = cvt_tf32(v.w);
            *(uint4*)&Bs[kk][n4] = u;
        }
        __syncthreads();

#pragma unroll
        for (int ks = 0; ks < BK; ks += 8) {
            uint32_t af[4][4];
#pragma unroll
            for (int mf = 0; mf < 4; mf++) {
                int mb = wm + mf * 16;
                af[mf][0] = As[ks + q    ][mb + g4    ];
                af[mf][1] = As[ks + q    ][mb + g4 + 8];
                af[mf][2] = As[ks + q + 4][mb + g4    ];
                af[mf][3] = As[ks + q + 4][mb + g4 + 8];
            }
#pragma unroll
            for (int nf = 0; nf < 4; nf++) {
                int nb = wn + nf * 8;
                uint32_t b0 = Bs[ks + q    ][nb + g4];
                uint32_t b1 = Bs[ks + q + 4][nb + g4];
#pragma unroll
                for (int mf = 0; mf < 4; mf++) {
                    asm volatile(
                        "mma.sync.aligned.m16n8k8.row.col.f32.tf32.tf32.f32 "
                        "{%0,%1,%2,%3},{%4,%5,%6,%7},{%8,%9},{%0,%1,%2,%3};"
                        : "+f"(acc[mf][nf][0]), "+f"(acc[mf][nf][1]),
                          "+f"(acc[mf][nf][2]), "+f"(acc[mf][nf][3])
                        : "r"(af[mf][0]), "r"(af[mf][1]),
                          "r"(af[mf][2]), "r"(af[mf][3]),
                          "r"(b0), "r"(b1));
                }
            }
        }
        __syncthreads();
    }

#pragma unroll
    for (int mf = 0; mf < 4; mf++) {
        int mrow = m0 + wm + mf * 16 + g4;
#pragma unroll
        for (int nf = 0; nf < 4; nf++) {
            int nc = n0 + wn + nf * 8 + 2 * q;
            *(__half2*)&Cb[(long)mrow * N + nc] =
                __floats2half2_rn(acc[mf][nf][0], acc[mf][nf][1]);
            *(__half2*)&Cb[(long)(mrow + 8) * N + nc] =
                __floats2half2_rn(acc[mf][nf][2], acc[mf][nf][3]);
        }
    }
}

// ---------------- fold: W_eff[b][o][h*32+d] = sum_e w_out[o][h*32+e]*ctxn[h][d][e]
__global__ __launch_bounds__(256)
void k_weff(const float* __restrict__ w_out)
{
    __shared__ float ctxn[HEADS][DH][DH + 1];
    __shared__ float zinv[HEADS * DH];
    int b = blockIdx.x, oc = blockIdx.y;
    int tid = threadIdx.x;
    if (tid < 128) zinv[tid] = 1.0f / g_z[b * 128 + tid];
    __syncthreads();
    for (int i = tid; i < 4096; i += 256) {
        int h = i >> 10, d = (i >> 5) & 31, e = i & 31;
        ctxn[h][d][e] = g_ctx[b * 4096 + i] * zinv[h * 32 + d];
    }
    __syncthreads();
    for (int i = tid; i < 8 * 128; i += 256) {
        int ol = i >> 7;
        int hd = i & 127;
        int h = hd >> 5, d = hd & 31;
        int o = oc * 8 + ol;
        const float* wrow = w_out + o * HID + h * 32;
        float s = 0.f;
#pragma unroll
        for (int e = 0; e < 32; e++) s = fmaf(wrow[e], ctxn[h][d][e], s);
        g_weff[((long)b * 256 + o) * HID + hd] = s;
    }
}

// ---------------- launch --------------------------------------------------
extern "C" void kernel_launch(void* const* d_in, const int* in_sizes, int n_in,
                              void* d_out, int out_size)
{
    const float *x = nullptr, *w_qkv = nullptr, *w_out = nullptr, *b_out = nullptr;
    for (int i = 0; i < n_in; i++) {
        const float* p = (const float*)d_in[i];
        if      (in_sizes[i] == BATCH * CIN * NPIX) x     = p;
        else if (in_sizes[i] == 3 * HID * CIN)      w_qkv = p;
        else if (in_sizes[i] == CIN * HID)          w_out = p;
        else if (in_sizes[i] == CIN)                b_out = p;
    }
    float* out = (float*)d_out;

    __half *xh, *kvh, *wh, *wtoth;
    float *weff;
    cudaGetSymbolAddress((void**)&xh,    g_xh);
    cudaGetSymbolAddress((void**)&kvh,   g_kvh);
    cudaGetSymbolAddress((void**)&wh,    g_wh);
    cudaGetSymbolAddress((void**)&wtoth, g_wtoth);
    cudaGetSymbolAddress((void**)&weff,  g_weff);

    cudaFuncSetAttribute(k_hgemm_async,
                         cudaFuncAttributeMaxDynamicSharedMemorySize, SMEM_G);
    cudaFuncSetAttribute(k_context_mma,
                         cudaFuncAttributeMaxDynamicSharedMemorySize, CTX_SMEM);

    // 0) zero accumulators + fp16 pre-convert
    k_zero<<<132, 256>>>();
    k_cvt<<<2048, 256>>>(x, w_qkv + 128 * CIN);

    // 1) kv = W_kv @ x  (fp16 pipelined GEMM, fp16 out)
    k_hgemm_async<<<dim3(NPIX / 128, 2, BATCH), 256, SMEM_G>>>(
        wh, 0,
        xh, (long)CIN * NPIX,
        kvh, (long)256 * NPIX,
        nullptr, 1);

    // 2) context via tensor cores (z via ones-mma, no shuffles)
    k_context_mma<<<dim3(32, HEADS, BATCH), 128, CTX_SMEM>>>();

    // 3a) fold w_out with normalized context -> W_eff (fp32)
    k_weff<<<dim3(BATCH, 32), 256>>>(w_out);

    // 3b) W_total[b] = W_eff[b] @ W_q  -> fp16 wtot
    k_sgemm_tc<<<dim3(2, 2, BATCH), 256>>>(
        weff, (long)256 * HID,
        w_qkv, 0,
        wtoth, (long)256 * 256,
        256, HID, 256);

    // 4) y[b] = W_total[b] @ x[b] + b_out  (fp16 pipelined GEMM, fp32 out)
    k_hgemm_async<<<dim3(NPIX / 128, 2, BATCH), 256, SMEM_G>>>(
        wtoth, (long)256 * 256,
        xh, (long)CIN * NPIX,
        out, (long)256 * NPIX,
        b_out, 0);
}